// round 2
// baseline (speedup 1.0000x reference)
#include <cuda_runtime.h>
#include <cstdint>

#define NB      32768      // batch
#define HH      512        // hidden
#define MDV     8          // meta embed dim
#define CDV     1024       // classifier dim
#define KIN     532        // H + 20
#define XS_STRIDE 546      // padded row stride (even, >= 544)
#define KPADT   17         // k-tiles of 32: 17*32 = 544 >= 532
#define EPSF    1e-6f

// ---- scratch (static device globals; no runtime allocation) ----
__device__ float g_meta_feat[NB * 20];
__device__ float g_features[(size_t)NB * CDV];

// ---------------------------------------------------------------------------
// packed fp32x2 FMA (Blackwell FFMA2) — 2 FMAs per instruction
// ---------------------------------------------------------------------------
__device__ __forceinline__ void ffma2(unsigned long long& d,
                                      unsigned long long a,
                                      unsigned long long b) {
    asm("fma.rn.f32x2 %0, %1, %2, %0;" : "+l"(d) : "l"(a), "l"(b));
}

__device__ __forceinline__ float f2_lo(unsigned long long v) {
    return __uint_as_float((unsigned)(v & 0xffffffffull));
}
__device__ __forceinline__ float f2_hi(unsigned long long v) {
    return __uint_as_float((unsigned)(v >> 32));
}

// ---------------------------------------------------------------------------
// K1: meta path. One thread per example.
//   - binary search the sorted cat_seg for [start,end)
//   - segment mean of 8-dim table rows
//   - 5 gathered meta embeds -> meta_mat[6][8]
//   - conv1d(6->5,k=3) + relu + maxpool3 -> meta_feat[20]
// ---------------------------------------------------------------------------
__global__ void meta_kernel(const float* __restrict__ meta_table,
                            const float* __restrict__ conv_w,
                            const float* __restrict__ conv_b,
                            const int*   __restrict__ meta_ids,
                            const int*   __restrict__ cat_ids,
                            const int*   __restrict__ cat_seg,
                            int ncat) {
    __shared__ float s_cw[90];
    __shared__ float s_cb[5];
    if (threadIdx.x < 90) s_cw[threadIdx.x] = conv_w[threadIdx.x];
    if (threadIdx.x < 5)  s_cb[threadIdx.x] = conv_b[threadIdx.x];
    __syncthreads();

    int b = blockIdx.x * blockDim.x + threadIdx.x;
    if (b >= NB) return;

    // lower_bound(b)
    int lo = 0, hi = ncat;
    while (lo < hi) { int m = (lo + hi) >> 1; if (cat_seg[m] < b) lo = m + 1; else hi = m; }
    int start = lo;
    // upper_bound(b)
    hi = ncat;
    while (lo < hi) { int m = (lo + hi) >> 1; if (cat_seg[m] <= b) lo = m + 1; else hi = m; }
    int end = lo;

    float mm[6][8];
    float sum[8];
#pragma unroll
    for (int d = 0; d < 8; d++) sum[d] = 0.f;
    for (int j = start; j < end; j++) {
        int id = cat_ids[j];
        const float* row = meta_table + (size_t)id * MDV;
#pragma unroll
        for (int d = 0; d < 8; d++) sum[d] += __ldg(row + d);
    }
    float cnt = fmaxf((float)(end - start), 1.f);
    float rc = 1.f / cnt;
#pragma unroll
    for (int d = 0; d < 8; d++) mm[0][d] = sum[d] * rc;

#pragma unroll
    for (int r = 0; r < 5; r++) {
        int id = meta_ids[b * 5 + r];
        const float* row = meta_table + (size_t)id * MDV;
#pragma unroll
        for (int d = 0; d < 8; d++) mm[r + 1][d] = __ldg(row + d);
    }

    float mf[20];
#pragma unroll
    for (int o = 0; o < 5; o++) {
        float cv[6];
#pragma unroll
        for (int t = 0; t < 6; t++) {
            float acc = s_cb[o];
#pragma unroll
            for (int i = 0; i < 6; i++)
#pragma unroll
                for (int k = 0; k < 3; k++)
                    acc = fmaf(s_cw[(o * 6 + i) * 3 + k], mm[i][t + k], acc);
            cv[t] = fmaxf(acc, 0.f);
        }
#pragma unroll
        for (int t = 0; t < 4; t++)
            mf[o * 4 + t] = fmaxf(fmaxf(cv[t], cv[t + 1]), cv[t + 2]);
    }
#pragma unroll
    for (int q = 0; q < 20; q++) g_meta_feat[b * 20 + q] = mf[q];
}

// ---------------------------------------------------------------------------
// K2: LN1(concat(encode, meta_feat)) -> GEMM1 (532 -> 1024) + ReLU
// Block: 256 threads, 64 rows. A in smem, W tiled through smem, FFMA2 core.
// ---------------------------------------------------------------------------
__global__ void __launch_bounds__(256, 1)
gemm1_kernel(const float* __restrict__ encode,
             const float* __restrict__ ln1_g,
             const float* __restrict__ ln1_b,
             const float* __restrict__ mlp1_w,
             const float* __restrict__ mlp1_b) {
    extern __shared__ float smem[];
    float*  xs  = smem;                                  // [64][XS_STRIDE]
    float2* wtp = (float2*)(smem + 64 * XS_STRIDE);      // [16][64] k-pairs x cols

    const int tid  = threadIdx.x;
    const int lane = tid & 31;
    const int wid  = tid >> 5;
    const int row0 = blockIdx.x * 64;

    // ---- Phase A: layernorm 64 input rows into xs ----
    for (int rr = 0; rr < 8; rr++) {
        int r  = wid * 8 + rr;
        int gr = row0 + r;
        float s = 0.f, s2 = 0.f;
        for (int k = lane; k < KIN; k += 32) {
            float v = (k < HH) ? encode[(size_t)gr * HH + k]
                               : g_meta_feat[gr * 20 + (k - HH)];
            xs[r * XS_STRIDE + k] = v;
            s += v; s2 = fmaf(v, v, s2);
        }
#pragma unroll
        for (int o = 16; o; o >>= 1) {
            s  += __shfl_xor_sync(0xffffffffu, s,  o);
            s2 += __shfl_xor_sync(0xffffffffu, s2, o);
        }
        float mu  = s * (1.f / (float)KIN);
        float var = fmaxf(s2 * (1.f / (float)KIN) - mu * mu, 0.f) + EPSF;
        float rinv = rsqrtf(var);
        rinv = rinv * (1.5f - 0.5f * var * rinv * rinv);   // Newton refine
        for (int k = lane; k < KIN; k += 32) {
            float v = xs[r * XS_STRIDE + k];
            xs[r * XS_STRIDE + k] = fmaf(ln1_g[k], (v - mu) * rinv, ln1_b[k]);
        }
        for (int k = KIN + lane; k < XS_STRIDE; k += 32)
            xs[r * XS_STRIDE + k] = 0.f;   // zero pad for k-tiles
    }
    __syncthreads();

    // ---- Phase B: GEMM. thread (ty,tx): rows ty+16i, cols jc*64 + j*16 + tx ----
    const int tx = tid & 15, ty = tid >> 4;
    const int scc = tid >> 2, ssub = tid & 3;   // staging roles

    for (int jc = 0; jc < 16; jc++) {
        unsigned long long acc[4][4];
#pragma unroll
        for (int i = 0; i < 4; i++)
#pragma unroll
            for (int j = 0; j < 4; j++) acc[i][j] = 0ull;

        for (int kt = 0; kt < KPADT; kt++) {
            __syncthreads();
            // stage W[64 cols][32 k] of this (jc, kt) tile as k-pairs
            {
                int col = jc * 64 + scc;
                int kg0 = kt * 32 + ssub * 8;
                const float* wrow = mlp1_w + (size_t)col * KIN;
                float v[8];
#pragma unroll
                for (int e = 0; e < 8; e++) {
                    int k = kg0 + e;
                    v[e] = (k < KIN) ? __ldg(wrow + k) : 0.f;
                }
#pragma unroll
                for (int p = 0; p < 4; p++)
                    wtp[(ssub * 4 + p) * 64 + scc] = make_float2(v[2 * p], v[2 * p + 1]);
            }
            __syncthreads();

            const int kb = kt * 32;
#pragma unroll
            for (int kk2 = 0; kk2 < 16; kk2++) {
                unsigned long long a2[4], b2[4];
#pragma unroll
                for (int i = 0; i < 4; i++)
                    a2[i] = *(const unsigned long long*)&xs[(ty + 16 * i) * XS_STRIDE + kb + 2 * kk2];
#pragma unroll
                for (int j = 0; j < 4; j++)
                    b2[j] = *(const unsigned long long*)&wtp[kk2 * 64 + j * 16 + tx];
#pragma unroll
                for (int i = 0; i < 4; i++)
#pragma unroll
                    for (int j = 0; j < 4; j++)
                        ffma2(acc[i][j], a2[i], b2[j]);
            }
        }

        // epilogue: horizontal add, +bias, ReLU, store
#pragma unroll
        for (int i = 0; i < 4; i++) {
            int gr = row0 + ty + 16 * i;
#pragma unroll
            for (int j = 0; j < 4; j++) {
                int col = jc * 64 + j * 16 + tx;
                float y = f2_lo(acc[i][j]) + f2_hi(acc[i][j]) + __ldg(mlp1_b + col);
                g_features[(size_t)gr * CDV + col] = fmaxf(y, 0.f);
            }
        }
    }
}

// ---------------------------------------------------------------------------
// K3: LN2 + GEMM2 (1024 -> 6) + out_b + normalized credit biases.
// One warp per row; features row held in 32 registers.
// ---------------------------------------------------------------------------
__global__ void __launch_bounds__(256)
head_kernel(const float* __restrict__ credit,
            const float* __restrict__ ln2_g,
            const float* __restrict__ ln2_b,
            const float* __restrict__ out_w,
            const float* __restrict__ out_b,
            float* __restrict__ out) {
    __shared__ float s_w[6 * CDV];
    __shared__ float s_g[CDV];
    __shared__ float s_b[CDV];
    __shared__ float s_ob[6];
    for (int i = threadIdx.x; i < 6 * CDV; i += 256) s_w[i] = out_w[i];
    for (int i = threadIdx.x; i < CDV; i += 256) { s_g[i] = ln2_g[i]; s_b[i] = ln2_b[i]; }
    if (threadIdx.x < 6) s_ob[threadIdx.x] = out_b[threadIdx.x];
    __syncthreads();

    const int lane = threadIdx.x & 31;
    const int w    = threadIdx.x >> 5;
    const int r    = blockIdx.x * 8 + w;

    const float* f = g_features + (size_t)r * CDV;
    float x[32];
    float s = 0.f, s2 = 0.f;
#pragma unroll
    for (int q = 0; q < 32; q++) {
        x[q] = f[lane + 32 * q];
        s += x[q]; s2 = fmaf(x[q], x[q], s2);
    }
#pragma unroll
    for (int o = 16; o; o >>= 1) {
        s  += __shfl_xor_sync(0xffffffffu, s,  o);
        s2 += __shfl_xor_sync(0xffffffffu, s2, o);
    }
    float mu  = s * (1.f / (float)CDV);
    float var = fmaxf(s2 * (1.f / (float)CDV) - mu * mu, 0.f) + EPSF;
    float rinv = rsqrtf(var);
    rinv = rinv * (1.5f - 0.5f * var * rinv * rinv);

    float acc[6] = {0.f, 0.f, 0.f, 0.f, 0.f, 0.f};
#pragma unroll
    for (int q = 0; q < 32; q++) {
        int k = lane + 32 * q;
        float zn = fmaf(s_g[k], (x[q] - mu) * rinv, s_b[k]);
#pragma unroll
        for (int o = 0; o < 6; o++)
            acc[o] = fmaf(zn, s_w[o * CDV + k], acc[o]);
    }
#pragma unroll
    for (int o = 0; o < 6; o++)
#pragma unroll
        for (int d = 16; d; d >>= 1)
            acc[o] += __shfl_xor_sync(0xffffffffu, acc[o], d);

    if (lane == 0) {
        float c[6], cs = 0.f;
#pragma unroll
        for (int o = 0; o < 6; o++) { c[o] = credit[r * 6 + o]; cs += c[o]; }
        float inv = (cs > 0.f) ? (1.f / cs) : 0.f;
#pragma unroll
        for (int o = 0; o < 6; o++) {
            float bias = (cs > 0.f) ? c[o] * inv : (1.f / 6.f);
            out[r * 6 + o] = acc[o] + s_ob[o] + bias;
        }
    }
}

// ---------------------------------------------------------------------------
extern "C" void kernel_launch(void* const* d_in, const int* in_sizes, int n_in,
                              void* d_out, int out_size) {
    const float* encode     = (const float*)d_in[0];
    const float* credit_vec = (const float*)d_in[1];
    const float* meta_table = (const float*)d_in[2];
    const float* conv_w     = (const float*)d_in[3];
    const float* conv_b     = (const float*)d_in[4];
    const float* ln1_g      = (const float*)d_in[5];
    const float* ln1_b      = (const float*)d_in[6];
    const float* mlp1_w     = (const float*)d_in[7];
    const float* mlp1_b     = (const float*)d_in[8];
    const float* ln2_g      = (const float*)d_in[9];
    const float* ln2_b      = (const float*)d_in[10];
    const float* out_w      = (const float*)d_in[11];
    const float* out_b      = (const float*)d_in[12];
    const int*   meta_ids   = (const int*)d_in[13];
    const int*   cat_ids    = (const int*)d_in[14];
    const int*   cat_seg    = (const int*)d_in[15];
    float*       out        = (float*)d_out;
    const int    ncat       = in_sizes[14];

    const int smem_bytes = (64 * XS_STRIDE + 16 * 64 * 2) * 4;  // 147,968 B
    cudaFuncSetAttribute(gemm1_kernel,
                         cudaFuncAttributeMaxDynamicSharedMemorySize, smem_bytes);

    meta_kernel<<<NB / 256, 256>>>(meta_table, conv_w, conv_b,
                                   meta_ids, cat_ids, cat_seg, ncat);
    gemm1_kernel<<<NB / 64, 256, smem_bytes>>>(encode, ln1_g, ln1_b,
                                               mlp1_w, mlp1_b);
    head_kernel<<<NB / 8, 256>>>(credit_vec, ln2_g, ln2_b, out_w, out_b, out);
}

// round 4
// speedup vs baseline: 3.3815x; 3.3815x over previous
#include <cuda_runtime.h>
#include <cuda_bf16.h>
#include <cstdint>

#define NB      32768      // batch
#define HH      512        // hidden
#define MDV     8          // meta embed dim
#define CDV     1024       // classifier dim
#define KIN     532        // H + 20
#define KPAD    576        // padded K
#define EPSF    1e-6f

// GEMM tiling
#define BM      128
#define BN      128
#define BK      32
#define NSTAGE  3
#define KCHUNKS 18         // 576 / 32

#define TSTRIDE 40                       // bf16 elems per smem row (80 B, conflict-free)
#define TILE_BYTES  (128 * TSTRIDE * 2)  // 10240
#define STAGE_BYTES (4 * TILE_BYTES)     // 40960 (Ah, Al, Bh, Bl)
#define SMEM_GEMM   (NSTAGE * STAGE_BYTES) // 122880

// ---- scratch (static device globals; no runtime allocation) ----
__device__ float         g_meta_feat[NB * 20];
__device__ float         g_features[(size_t)NB * CDV];
__device__ __nv_bfloat16 g_Ahi[(size_t)NB * KPAD];
__device__ __nv_bfloat16 g_Alo[(size_t)NB * KPAD];
__device__ __nv_bfloat16 g_Whi[(size_t)CDV * KPAD];
__device__ __nv_bfloat16 g_Wlo[(size_t)CDV * KPAD];

// ---------------------------------------------------------------------------
// PTX helpers (baseline PTX only — no tcgen05 on this build)
// ---------------------------------------------------------------------------
__device__ __forceinline__ uint32_t smem_u32(const void* p) {
    uint32_t a;
    asm("{ .reg .u64 t; cvta.to.shared.u64 t, %1; cvt.u32.u64 %0, t; }"
        : "=r"(a) : "l"(p));
    return a;
}

__device__ __forceinline__ void cp16(uint32_t s, const void* g) {
    asm volatile("cp.async.cg.shared.global [%0], [%1], 16;" :: "r"(s), "l"(g));
}
__device__ __forceinline__ void cp_commit() {
    asm volatile("cp.async.commit_group;" ::: "memory");
}
template <int N>
__device__ __forceinline__ void cp_wait() {
    asm volatile("cp.async.wait_group %0;" :: "n"(N) : "memory");
}

__device__ __forceinline__ void ldsm4(uint32_t* r, uint32_t a) {
    asm volatile("ldmatrix.sync.aligned.m8n8.x4.shared.b16 {%0,%1,%2,%3}, [%4];"
                 : "=r"(r[0]), "=r"(r[1]), "=r"(r[2]), "=r"(r[3]) : "r"(a));
}

__device__ __forceinline__ void mma16816(float* c, const uint32_t* a, const uint32_t* b) {
    asm volatile("mma.sync.aligned.m16n8k16.row.col.f32.bf16.bf16.f32 "
                 "{%0,%1,%2,%3}, {%4,%5,%6,%7}, {%8,%9}, {%0,%1,%2,%3};"
                 : "+f"(c[0]), "+f"(c[1]), "+f"(c[2]), "+f"(c[3])
                 : "r"(a[0]), "r"(a[1]), "r"(a[2]), "r"(a[3]),
                   "r"(b[0]), "r"(b[1]));
}

// ---------------------------------------------------------------------------
// K1: meta path. One thread per example (22 us measured — fine).
// ---------------------------------------------------------------------------
__global__ void meta_kernel(const float* __restrict__ meta_table,
                            const float* __restrict__ conv_w,
                            const float* __restrict__ conv_b,
                            const int*   __restrict__ meta_ids,
                            const int*   __restrict__ cat_ids,
                            const int*   __restrict__ cat_seg,
                            int ncat) {
    __shared__ float s_cw[90];
    __shared__ float s_cb[5];
    if (threadIdx.x < 90) s_cw[threadIdx.x] = conv_w[threadIdx.x];
    if (threadIdx.x < 5)  s_cb[threadIdx.x] = conv_b[threadIdx.x];
    __syncthreads();

    int b = blockIdx.x * blockDim.x + threadIdx.x;
    if (b >= NB) return;

    int lo = 0, hi = ncat;
    while (lo < hi) { int m = (lo + hi) >> 1; if (cat_seg[m] < b) lo = m + 1; else hi = m; }
    int start = lo;
    hi = ncat;
    while (lo < hi) { int m = (lo + hi) >> 1; if (cat_seg[m] <= b) lo = m + 1; else hi = m; }
    int end = lo;

    float mm[6][8];
    float sum[8];
#pragma unroll
    for (int d = 0; d < 8; d++) sum[d] = 0.f;
    for (int j = start; j < end; j++) {
        int id = cat_ids[j];
        const float* row = meta_table + (size_t)id * MDV;
#pragma unroll
        for (int d = 0; d < 8; d++) sum[d] += __ldg(row + d);
    }
    float cnt = fmaxf((float)(end - start), 1.f);
    float rc = 1.f / cnt;
#pragma unroll
    for (int d = 0; d < 8; d++) mm[0][d] = sum[d] * rc;

#pragma unroll
    for (int r = 0; r < 5; r++) {
        int id = meta_ids[b * 5 + r];
        const float* row = meta_table + (size_t)id * MDV;
#pragma unroll
        for (int d = 0; d < 8; d++) mm[r + 1][d] = __ldg(row + d);
    }

    float mf[20];
#pragma unroll
    for (int o = 0; o < 5; o++) {
        float cv[6];
#pragma unroll
        for (int t = 0; t < 6; t++) {
            float acc = s_cb[o];
#pragma unroll
            for (int i = 0; i < 6; i++)
#pragma unroll
                for (int k = 0; k < 3; k++)
                    acc = fmaf(s_cw[(o * 6 + i) * 3 + k], mm[i][t + k], acc);
            cv[t] = fmaxf(acc, 0.f);
        }
#pragma unroll
        for (int t = 0; t < 4; t++)
            mf[o * 4 + t] = fmaxf(fmaxf(cv[t], cv[t + 1]), cv[t + 2]);
    }
#pragma unroll
    for (int q = 0; q < 20; q++) g_meta_feat[b * 20 + q] = mf[q];
}

// ---------------------------------------------------------------------------
// K2: LN1(concat(encode, meta_feat)) -> bf16 hi/lo split rows [NB][KPAD].
// ---------------------------------------------------------------------------
__global__ void __launch_bounds__(256)
prep_kernel(const float* __restrict__ encode,
            const float* __restrict__ ln1_g,
            const float* __restrict__ ln1_b) {
    const int lane = threadIdx.x & 31;
    const int wid  = threadIdx.x >> 5;
    const int r    = blockIdx.x * 8 + wid;

    float x[17];
    float s = 0.f, s2 = 0.f;
#pragma unroll
    for (int q = 0; q < 17; q++) {
        int k = lane + 32 * q;
        float v = 0.f;
        if (k < KIN)
            v = (k < HH) ? encode[(size_t)r * HH + k]
                         : g_meta_feat[r * 20 + (k - HH)];
        x[q] = v;
        s += v; s2 = fmaf(v, v, s2);
    }
#pragma unroll
    for (int o = 16; o; o >>= 1) {
        s  += __shfl_xor_sync(0xffffffffu, s,  o);
        s2 += __shfl_xor_sync(0xffffffffu, s2, o);
    }
    float mu  = s * (1.f / (float)KIN);
    float var = fmaxf(s2 * (1.f / (float)KIN) - mu * mu, 0.f) + EPSF;
    float rinv = rsqrtf(var);
    rinv = rinv * (1.5f - 0.5f * var * rinv * rinv);

    __nv_bfloat16* ah = g_Ahi + (size_t)r * KPAD;
    __nv_bfloat16* al = g_Alo + (size_t)r * KPAD;
#pragma unroll
    for (int q = 0; q < 18; q++) {
        int k = lane + 32 * q;
        if (k >= KPAD) break;
        float v = 0.f;
        if (k < KIN)
            v = fmaf(__ldg(ln1_g + k), ((k < 544 ? x[q & 16 ? 16 : q] : 0.f), (x[q > 16 ? 16 : q] - mu)) * rinv, __ldg(ln1_b + k));
        // (note: q ranges 0..17; x[] valid for q<17, k>=544 implies q==17 -> v stays 0 via k<KIN check)
        if (k >= KIN) v = 0.f;
        __nv_bfloat16 h = __float2bfloat16(v);
        __nv_bfloat16 l = __float2bfloat16(v - __bfloat162float(h));
        ah[k] = h;
        al[k] = l;
    }
}

// ---------------------------------------------------------------------------
// K3: W -> bf16 hi/lo split [CDV][KPAD], zero-padded.
// ---------------------------------------------------------------------------
__global__ void __launch_bounds__(256)
wsplit_kernel(const float* __restrict__ mlp1_w) {
    const int lane = threadIdx.x & 31;
    const int wid  = threadIdx.x >> 5;
    const int r    = blockIdx.x * 8 + wid;

    __nv_bfloat16* wh = g_Whi + (size_t)r * KPAD;
    __nv_bfloat16* wl = g_Wlo + (size_t)r * KPAD;
    for (int k = lane; k < KPAD; k += 32) {
        float v = (k < KIN) ? mlp1_w[(size_t)r * KIN + k] : 0.f;
        __nv_bfloat16 h = __float2bfloat16(v);
        __nv_bfloat16 l = __float2bfloat16(v - __bfloat162float(h));
        wh[k] = h;
        wl[k] = l;
    }
}

// ---------------------------------------------------------------------------
// K4: HMMA GEMM1: features = relu(A @ W^T + b), bf16 hi/lo 3-pass split.
// CTA 128x128, BK=32, 3-stage cp.async pipeline, ldmatrix + mma.sync.
// ---------------------------------------------------------------------------
__global__ void __launch_bounds__(256)
gemm1_hmma(const float* __restrict__ mlp1_b) {
    extern __shared__ char smem[];
    const uint32_t sbase = smem_u32(smem);
    const int tid  = threadIdx.x;
    const int lane = tid & 31;
    const int wid  = tid >> 5;
    const int wm   = wid >> 1;          // 0..3 : 32-row slice
    const int wn   = wid & 1;           // 0..1 : 64-col slice
    const int mt   = blockIdx.x >> 3;
    const int nt   = blockIdx.x & 7;
    const int row0 = mt * BM;
    const int n0   = nt * BN;

    const __nv_bfloat16* gsrc[4] = {
        g_Ahi + (size_t)row0 * KPAD,
        g_Alo + (size_t)row0 * KPAD,
        g_Whi + (size_t)n0   * KPAD,
        g_Wlo + (size_t)n0   * KPAD };

    // per-thread staging coords: 512 (row,seg) pairs per tile, 2 per thread
    const int r_a = tid >> 1;                 // not used; explicit below
    (void)r_a;

    auto load_stage = [&](int c, int st) {
        const int k0 = c * BK;
        const uint32_t sst = sbase + st * STAGE_BYTES;
#pragma unroll
        for (int t = 0; t < 4; t++) {
#pragma unroll
            for (int h = 0; h < 2; h++) {
                int idx = tid + h * 256;
                int row = idx >> 2, seg = idx & 3;
                cp16(sst + t * TILE_BYTES + (row * TSTRIDE + seg * 8) * 2,
                     gsrc[t] + (size_t)row * KPAD + k0 + seg * 8);
            }
        }
    };

    float acc[2][8][4];
#pragma unroll
    for (int i = 0; i < 2; i++)
#pragma unroll
        for (int j = 0; j < 8; j++)
#pragma unroll
            for (int e = 0; e < 4; e++) acc[i][j][e] = 0.f;

    load_stage(0, 0); cp_commit();
    load_stage(1, 1); cp_commit();

    // precomputed lane-dependent smem offsets (bytes)
    const uint32_t a_off0 = ((wm * 32 + (lane & 15)) * TSTRIDE + (lane >> 4) * 8) * 2;
    const uint32_t b_off0 = ((wn * 64 + ((lane >> 4) << 3) + (lane & 7)) * TSTRIDE
                             + (lane & 8)) * 2;

    for (int c = 0; c < KCHUNKS; c++) {
        cp_wait<NSTAGE - 2>();
        __syncthreads();
        // prefetch stage c+2 into the buffer freed by chunk c-1
        if (c + 2 < KCHUNKS) load_stage(c + 2, (c + 2) % NSTAGE);
        cp_commit();

        const uint32_t aH = sbase + (c % NSTAGE) * STAGE_BYTES;
        const uint32_t aL = aH + TILE_BYTES;
        const uint32_t bH = aL + TILE_BYTES;
        const uint32_t bL = bH + TILE_BYTES;

#pragma unroll
        for (int ks = 0; ks < 2; ks++) {
            uint32_t ah[2][4], al[2][4];
#pragma unroll
            for (int mf = 0; mf < 2; mf++) {
                uint32_t ao = a_off0 + (mf * 16 * TSTRIDE + ks * 16) * 2;
                ldsm4(ah[mf], aH + ao);
                ldsm4(al[mf], aL + ao);
            }
#pragma unroll
            for (int nf2 = 0; nf2 < 4; nf2++) {
                uint32_t bo = b_off0 + (nf2 * 16 * TSTRIDE + ks * 16) * 2;
                uint32_t bh[4], bl[4];
                ldsm4(bh, bH + bo);
                ldsm4(bl, bL + bo);
#pragma unroll
                for (int mf = 0; mf < 2; mf++) {
                    mma16816(acc[mf][2 * nf2 + 0], ah[mf], bh + 0);
                    mma16816(acc[mf][2 * nf2 + 1], ah[mf], bh + 2);
                    mma16816(acc[mf][2 * nf2 + 0], ah[mf], bl + 0);
                    mma16816(acc[mf][2 * nf2 + 1], ah[mf], bl + 2);
                    mma16816(acc[mf][2 * nf2 + 0], al[mf], bh + 0);
                    mma16816(acc[mf][2 * nf2 + 1], al[mf], bh + 2);
                }
            }
        }
        __syncthreads();
    }

    // ---- epilogue: bias + relu, direct stores (32B sectors per quad) ----
    const int l4 = lane >> 2, l2 = lane & 3;
#pragma unroll
    for (int mf = 0; mf < 2; mf++) {
        int row = row0 + wm * 32 + mf * 16 + l4;
#pragma unroll
        for (int nf = 0; nf < 8; nf++) {
            int col = n0 + wn * 64 + nf * 8 + 2 * l2;
            float2 bb = *(const float2*)(mlp1_b + col);
            float2 v0, v1;
            v0.x = fmaxf(acc[mf][nf][0] + bb.x, 0.f);
            v0.y = fmaxf(acc[mf][nf][1] + bb.y, 0.f);
            v1.x = fmaxf(acc[mf][nf][2] + bb.x, 0.f);
            v1.y = fmaxf(acc[mf][nf][3] + bb.y, 0.f);
            *(float2*)(g_features + (size_t)row * CDV + col)       = v0;
            *(float2*)(g_features + (size_t)(row + 8) * CDV + col) = v1;
        }
    }
}

// ---------------------------------------------------------------------------
// K5: LN2 + GEMM2 (1024 -> 6) + out_b + normalized credit biases.
// ---------------------------------------------------------------------------
__global__ void __launch_bounds__(256)
head_kernel(const float* __restrict__ credit,
            const float* __restrict__ ln2_g,
            const float* __restrict__ ln2_b,
            const float* __restrict__ out_w,
            const float* __restrict__ out_b,
            float* __restrict__ out) {
    __shared__ float s_w[6 * CDV];
    __shared__ float s_g[CDV];
    __shared__ float s_b[CDV];
    __shared__ float s_ob[6];
    for (int i = threadIdx.x; i < 6 * CDV; i += 256) s_w[i] = out_w[i];
    for (int i = threadIdx.x; i < CDV; i += 256) { s_g[i] = ln2_g[i]; s_b[i] = ln2_b[i]; }
    if (threadIdx.x < 6) s_ob[threadIdx.x] = out_b[threadIdx.x];
    __syncthreads();

    const int lane = threadIdx.x & 31;
    const int w    = threadIdx.x >> 5;
    const int r    = blockIdx.x * 8 + w;

    const float* f = g_features + (size_t)r * CDV;
    float x[32];
    float s = 0.f, s2 = 0.f;
#pragma unroll
    for (int q = 0; q < 32; q++) {
        x[q] = f[lane + 32 * q];
        s += x[q]; s2 = fmaf(x[q], x[q], s2);
    }
#pragma unroll
    for (int o = 16; o; o >>= 1) {
        s  += __shfl_xor_sync(0xffffffffu, s,  o);
        s2 += __shfl_xor_sync(0xffffffffu, s2, o);
    }
    float mu  = s * (1.f / (float)CDV);
    float var = fmaxf(s2 * (1.f / (float)CDV) - mu * mu, 0.f) + EPSF;
    float rinv = rsqrtf(var);
    rinv = rinv * (1.5f - 0.5f * var * rinv * rinv);

    float acc[6] = {0.f, 0.f, 0.f, 0.f, 0.f, 0.f};
#pragma unroll
    for (int q = 0; q < 32; q++) {
        int k = lane + 32 * q;
        float zn = fmaf(s_g[k], (x[q] - mu) * rinv, s_b[k]);
#pragma unroll
        for (int o = 0; o < 6; o++)
            acc[o] = fmaf(zn, s_w[o * CDV + k], acc[o]);
    }
#pragma unroll
    for (int o = 0; o < 6; o++)
#pragma unroll
        for (int d = 16; d; d >>= 1)
            acc[o] += __shfl_xor_sync(0xffffffffu, acc[o], d);

    if (lane == 0) {
        float cvals[6], cs = 0.f;
#pragma unroll
        for (int o = 0; o < 6; o++) { cvals[o] = credit[r * 6 + o]; cs += cvals[o]; }
        float inv = (cs > 0.f) ? (1.f / cs) : 0.f;
#pragma unroll
        for (int o = 0; o < 6; o++) {
            float bias = (cs > 0.f) ? cvals[o] * inv : (1.f / 6.f);
            out[r * 6 + o] = acc[o] + s_ob[o] + bias;
        }
    }
}

// ---------------------------------------------------------------------------
extern "C" void kernel_launch(void* const* d_in, const int* in_sizes, int n_in,
                              void* d_out, int out_size) {
    const float* encode     = (const float*)d_in[0];
    const float* credit_vec = (const float*)d_in[1];
    const float* meta_table = (const float*)d_in[2];
    const float* conv_w     = (const float*)d_in[3];
    const float* conv_b     = (const float*)d_in[4];
    const float* ln1_g      = (const float*)d_in[5];
    const float* ln1_b      = (const float*)d_in[6];
    const float* mlp1_w     = (const float*)d_in[7];
    const float* mlp1_b     = (const float*)d_in[8];
    const float* ln2_g      = (const float*)d_in[9];
    const float* ln2_b      = (const float*)d_in[10];
    const float* out_w      = (const float*)d_in[11];
    const float* out_b      = (const float*)d_in[12];
    const int*   meta_ids   = (const int*)d_in[13];
    const int*   cat_ids    = (const int*)d_in[14];
    const int*   cat_seg    = (const int*)d_in[15];
    float*       out        = (float*)d_out;
    const int    ncat       = in_sizes[14];

    cudaFuncSetAttribute(gemm1_hmma,
                         cudaFuncAttributeMaxDynamicSharedMemorySize, SMEM_GEMM);

    meta_kernel<<<NB / 256, 256>>>(meta_table, conv_w, conv_b,
                                   meta_ids, cat_ids, cat_seg, ncat);
    wsplit_kernel<<<CDV / 8, 256>>>(mlp1_w);
    prep_kernel<<<NB / 8, 256>>>(encode, ln1_g, ln1_b);
    gemm1_hmma<<<(NB / BM) * (CDV / BN), 256, SMEM_GEMM>>>(mlp1_b);
    head_kernel<<<NB / 8, 256>>>(credit_vec, ln2_g, ln2_b, out_w, out_b, out);
}

// round 5
// speedup vs baseline: 4.9512x; 1.4642x over previous
#include <cuda_runtime.h>
#include <cuda_fp16.h>
#include <cstdint>

#define NB      32768      // batch
#define HH      512        // hidden
#define MDV     8          // meta embed dim
#define CDV     1024       // classifier dim
#define KIN     532        // H + 20
#define KPAD    576        // padded K
#define EPSF    1e-6f

// GEMM tiling
#define BM      128
#define BN      128
#define BK      32
#define NSTAGE  3
#define KCHUNKS 18         // 576 / 32

#define TSTRIDE 40                       // fp16 elems per smem row (80 B, conflict-free)
#define TILE_BYTES  (128 * TSTRIDE * 2)  // 10240
#define STAGE_BYTES (3 * TILE_BYTES)     // 30720 (Ah, Wh, Wl)
#define SMEM_GEMM   (NSTAGE * STAGE_BYTES) // 92160

// ---- scratch (static device globals; no runtime allocation) ----
__device__ float  g_meta_feat[NB * 20];
__device__ float  g_features[(size_t)NB * CDV];
__device__ __half g_Ah[(size_t)NB * KPAD];
__device__ __half g_Wh[(size_t)CDV * KPAD];
__device__ __half g_Wl[(size_t)CDV * KPAD];

// ---------------------------------------------------------------------------
// PTX helpers (baseline PTX only — tcgen05 unavailable on this build)
// ---------------------------------------------------------------------------
__device__ __forceinline__ uint32_t smem_u32(const void* p) {
    uint32_t a;
    asm("{ .reg .u64 t; cvta.to.shared.u64 t, %1; cvt.u32.u64 %0, t; }"
        : "=r"(a) : "l"(p));
    return a;
}

__device__ __forceinline__ void cp16(uint32_t s, const void* g) {
    asm volatile("cp.async.cg.shared.global [%0], [%1], 16;" :: "r"(s), "l"(g));
}
__device__ __forceinline__ void cp_commit() {
    asm volatile("cp.async.commit_group;" ::: "memory");
}
template <int N>
__device__ __forceinline__ void cp_wait() {
    asm volatile("cp.async.wait_group %0;" :: "n"(N) : "memory");
}

__device__ __forceinline__ void ldsm4(uint32_t* r, uint32_t a) {
    asm volatile("ldmatrix.sync.aligned.m8n8.x4.shared.b16 {%0,%1,%2,%3}, [%4];"
                 : "=r"(r[0]), "=r"(r[1]), "=r"(r[2]), "=r"(r[3]) : "r"(a));
}

__device__ __forceinline__ void mma16816(float* c, const uint32_t* a, const uint32_t* b) {
    asm volatile("mma.sync.aligned.m16n8k16.row.col.f32.f16.f16.f32 "
                 "{%0,%1,%2,%3}, {%4,%5,%6,%7}, {%8,%9}, {%0,%1,%2,%3};"
                 : "+f"(c[0]), "+f"(c[1]), "+f"(c[2]), "+f"(c[3])
                 : "r"(a[0]), "r"(a[1]), "r"(a[2]), "r"(a[3]),
                   "r"(b[0]), "r"(b[1]));
}

// ---------------------------------------------------------------------------
// K1: meta path. One thread per example (22 us measured — fine).
// ---------------------------------------------------------------------------
__global__ void meta_kernel(const float* __restrict__ meta_table,
                            const float* __restrict__ conv_w,
                            const float* __restrict__ conv_b,
                            const int*   __restrict__ meta_ids,
                            const int*   __restrict__ cat_ids,
                            const int*   __restrict__ cat_seg,
                            int ncat) {
    __shared__ float s_cw[90];
    __shared__ float s_cb[5];
    if (threadIdx.x < 90) s_cw[threadIdx.x] = conv_w[threadIdx.x];
    if (threadIdx.x < 5)  s_cb[threadIdx.x] = conv_b[threadIdx.x];
    __syncthreads();

    int b = blockIdx.x * blockDim.x + threadIdx.x;
    if (b >= NB) return;

    int lo = 0, hi = ncat;
    while (lo < hi) { int m = (lo + hi) >> 1; if (cat_seg[m] < b) lo = m + 1; else hi = m; }
    int start = lo;
    hi = ncat;
    while (lo < hi) { int m = (lo + hi) >> 1; if (cat_seg[m] <= b) lo = m + 1; else hi = m; }
    int end = lo;

    float mm[6][8];
    float sum[8];
#pragma unroll
    for (int d = 0; d < 8; d++) sum[d] = 0.f;
    for (int j = start; j < end; j++) {
        int id = cat_ids[j];
        const float* row = meta_table + (size_t)id * MDV;
#pragma unroll
        for (int d = 0; d < 8; d++) sum[d] += __ldg(row + d);
    }
    float cnt = fmaxf((float)(end - start), 1.f);
    float rc = 1.f / cnt;
#pragma unroll
    for (int d = 0; d < 8; d++) mm[0][d] = sum[d] * rc;

#pragma unroll
    for (int r = 0; r < 5; r++) {
        int id = meta_ids[b * 5 + r];
        const float* row = meta_table + (size_t)id * MDV;
#pragma unroll
        for (int d = 0; d < 8; d++) mm[r + 1][d] = __ldg(row + d);
    }

    float mf[20];
#pragma unroll
    for (int o = 0; o < 5; o++) {
        float cv[6];
#pragma unroll
        for (int t = 0; t < 6; t++) {
            float acc = s_cb[o];
#pragma unroll
            for (int i = 0; i < 6; i++)
#pragma unroll
                for (int k = 0; k < 3; k++)
                    acc = fmaf(s_cw[(o * 6 + i) * 3 + k], mm[i][t + k], acc);
            cv[t] = fmaxf(acc, 0.f);
        }
#pragma unroll
        for (int t = 0; t < 4; t++)
            mf[o * 4 + t] = fmaxf(fmaxf(cv[t], cv[t + 1]), cv[t + 2]);
    }
#pragma unroll
    for (int q = 0; q < 20; q++) g_meta_feat[b * 20 + q] = mf[q];
}

// ---------------------------------------------------------------------------
// K2: LN1(concat(encode, meta_feat)) -> fp16 rows [NB][KPAD] (zero-padded).
// One warp per row.
// ---------------------------------------------------------------------------
__global__ void __launch_bounds__(256)
prep_kernel(const float* __restrict__ encode,
            const float* __restrict__ ln1_g,
            const float* __restrict__ ln1_b) {
    const int lane = threadIdx.x & 31;
    const int wid  = threadIdx.x >> 5;
    const int r    = blockIdx.x * 8 + wid;

    float x[17];
    float s = 0.f, s2 = 0.f;
#pragma unroll
    for (int q = 0; q < 17; q++) {
        int k = lane + 32 * q;
        float v = 0.f;
        if (k < KIN)
            v = (k < HH) ? encode[(size_t)r * HH + k]
                         : g_meta_feat[r * 20 + (k - HH)];
        x[q] = v;
        s += v; s2 = fmaf(v, v, s2);
    }
#pragma unroll
    for (int o = 16; o; o >>= 1) {
        s  += __shfl_xor_sync(0xffffffffu, s,  o);
        s2 += __shfl_xor_sync(0xffffffffu, s2, o);
    }
    float mu  = s * (1.f / (float)KIN);
    float var = fmaxf(s2 * (1.f / (float)KIN) - mu * mu, 0.f) + EPSF;
    float rinv = rsqrtf(var);
    rinv = rinv * (1.5f - 0.5f * var * rinv * rinv);

    __half* ah = g_Ah + (size_t)r * KPAD;
#pragma unroll
    for (int q = 0; q < 18; q++) {
        int k = lane + 32 * q;
        if (k >= KPAD) continue;
        float v = 0.f;
        if (k < KIN) {   // implies q <= 16, x[q] valid
            v = fmaf(__ldg(ln1_g + k), (x[q < 17 ? q : 0] - mu) * rinv, __ldg(ln1_b + k));
        }
        ah[k] = __float2half_rn(v);
    }
}

// ---------------------------------------------------------------------------
// K3: W -> fp16 hi/lo split [CDV][KPAD], zero-padded.
// ---------------------------------------------------------------------------
__global__ void __launch_bounds__(256)
wsplit_kernel(const float* __restrict__ mlp1_w) {
    const int lane = threadIdx.x & 31;
    const int wid  = threadIdx.x >> 5;
    const int r    = blockIdx.x * 8 + wid;

    __half* wh = g_Wh + (size_t)r * KPAD;
    __half* wl = g_Wl + (size_t)r * KPAD;
    for (int k = lane; k < KPAD; k += 32) {
        float v = (k < KIN) ? mlp1_w[(size_t)r * KIN + k] : 0.f;
        __half h = __float2half_rn(v);
        __half l = __float2half_rn(v - __half2float(h));
        wh[k] = h;
        wl[k] = l;
    }
}

// ---------------------------------------------------------------------------
// K4: HMMA GEMM1: features = relu(A @ W^T + b), fp16 2-pass (A·Wh + A·Wl).
// CTA 128x128, BK=32, 3-stage cp.async pipeline, 2 CTAs/SM.
// ---------------------------------------------------------------------------
__global__ void __launch_bounds__(256, 2)
gemm1_hmma(const float* __restrict__ mlp1_b) {
    extern __shared__ char smem[];
    const uint32_t sbase = smem_u32(smem);
    const int tid  = threadIdx.x;
    const int lane = tid & 31;
    const int wid  = tid >> 5;
    const int wm   = wid >> 1;          // 0..3 : 32-row slice
    const int wn   = wid & 1;           // 0..1 : 64-col slice
    const int mt   = blockIdx.x >> 3;
    const int nt   = blockIdx.x & 7;
    const int row0 = mt * BM;
    const int n0   = nt * BN;

    const __half* gsrc[3] = {
        g_Ah + (size_t)row0 * KPAD,
        g_Wh + (size_t)n0   * KPAD,
        g_Wl + (size_t)n0   * KPAD };

    auto load_stage = [&](int c, int st) {
        const int k0 = c * BK;
        const uint32_t sst = sbase + st * STAGE_BYTES;
#pragma unroll
        for (int t = 0; t < 3; t++) {
#pragma unroll
            for (int h = 0; h < 2; h++) {
                int idx = tid + h * 256;
                int row = idx >> 2, seg = idx & 3;
                cp16(sst + t * TILE_BYTES + (row * TSTRIDE + seg * 8) * 2,
                     gsrc[t] + (size_t)row * KPAD + k0 + seg * 8);
            }
        }
    };

    float acc[2][8][4];
#pragma unroll
    for (int i = 0; i < 2; i++)
#pragma unroll
        for (int j = 0; j < 8; j++)
#pragma unroll
            for (int e = 0; e < 4; e++) acc[i][j][e] = 0.f;

    load_stage(0, 0); cp_commit();
    load_stage(1, 1); cp_commit();

    // lane-dependent smem offsets (bytes)
    const uint32_t a_off0 = ((wm * 32 + (lane & 15)) * TSTRIDE + (lane >> 4) * 8) * 2;
    const uint32_t b_off0 = ((wn * 64 + ((lane >> 4) << 3) + (lane & 7)) * TSTRIDE
                             + (lane & 8)) * 2;

    for (int c = 0; c < KCHUNKS; c++) {
        cp_wait<NSTAGE - 2>();
        __syncthreads();
        if (c + 2 < KCHUNKS) load_stage(c + 2, (c + 2) % NSTAGE);
        cp_commit();

        const uint32_t aT = sbase + (c % NSTAGE) * STAGE_BYTES;
        const uint32_t bH = aT + TILE_BYTES;
        const uint32_t bL = bH + TILE_BYTES;

#pragma unroll
        for (int ks = 0; ks < 2; ks++) {
            uint32_t af[2][4], bh[4][4], bl[4][4];
#pragma unroll
            for (int mf = 0; mf < 2; mf++)
                ldsm4(af[mf], aT + a_off0 + (mf * 16 * TSTRIDE + ks * 16) * 2);
#pragma unroll
            for (int nf2 = 0; nf2 < 4; nf2++) {
                uint32_t bo = b_off0 + (nf2 * 16 * TSTRIDE + ks * 16) * 2;
                ldsm4(bh[nf2], bH + bo);
                ldsm4(bl[nf2], bL + bo);
            }
            // pass 1: A * Whi  (each acc touched once per 16-MMA sweep)
#pragma unroll
            for (int nf2 = 0; nf2 < 4; nf2++)
#pragma unroll
                for (int mf = 0; mf < 2; mf++) {
                    mma16816(acc[mf][2 * nf2 + 0], af[mf], bh[nf2] + 0);
                    mma16816(acc[mf][2 * nf2 + 1], af[mf], bh[nf2] + 2);
                }
            // pass 2: A * Wlo
#pragma unroll
            for (int nf2 = 0; nf2 < 4; nf2++)
#pragma unroll
                for (int mf = 0; mf < 2; mf++) {
                    mma16816(acc[mf][2 * nf2 + 0], af[mf], bl[nf2] + 0);
                    mma16816(acc[mf][2 * nf2 + 1], af[mf], bl[nf2] + 2);
                }
        }
        __syncthreads();
    }

    // ---- epilogue: bias + relu, direct stores ----
    const int l4 = lane >> 2, l2 = lane & 3;
#pragma unroll
    for (int mf = 0; mf < 2; mf++) {
        int row = row0 + wm * 32 + mf * 16 + l4;
#pragma unroll
        for (int nf = 0; nf < 8; nf++) {
            int col = n0 + wn * 64 + nf * 8 + 2 * l2;
            float2 bb = *(const float2*)(mlp1_b + col);
            float2 v0, v1;
            v0.x = fmaxf(acc[mf][nf][0] + bb.x, 0.f);
            v0.y = fmaxf(acc[mf][nf][1] + bb.y, 0.f);
            v1.x = fmaxf(acc[mf][nf][2] + bb.x, 0.f);
            v1.y = fmaxf(acc[mf][nf][3] + bb.y, 0.f);
            *(float2*)(g_features + (size_t)row * CDV + col)       = v0;
            *(float2*)(g_features + (size_t)(row + 8) * CDV + col) = v1;
        }
    }
}

// ---------------------------------------------------------------------------
// K5: LN2 + GEMM2 (1024 -> 6) + out_b + normalized credit biases.
// ---------------------------------------------------------------------------
__global__ void __launch_bounds__(256)
head_kernel(const float* __restrict__ credit,
            const float* __restrict__ ln2_g,
            const float* __restrict__ ln2_b,
            const float* __restrict__ out_w,
            const float* __restrict__ out_b,
            float* __restrict__ out) {
    __shared__ float s_w[6 * CDV];
    __shared__ float s_g[CDV];
    __shared__ float s_b[CDV];
    __shared__ float s_ob[6];
    for (int i = threadIdx.x; i < 6 * CDV; i += 256) s_w[i] = out_w[i];
    for (int i = threadIdx.x; i < CDV; i += 256) { s_g[i] = ln2_g[i]; s_b[i] = ln2_b[i]; }
    if (threadIdx.x < 6) s_ob[threadIdx.x] = out_b[threadIdx.x];
    __syncthreads();

    const int lane = threadIdx.x & 31;
    const int w    = threadIdx.x >> 5;
    const int r    = blockIdx.x * 8 + w;

    const float* f = g_features + (size_t)r * CDV;
    float x[32];
    float s = 0.f, s2 = 0.f;
#pragma unroll
    for (int q = 0; q < 32; q++) {
        x[q] = f[lane + 32 * q];
        s += x[q]; s2 = fmaf(x[q], x[q], s2);
    }
#pragma unroll
    for (int o = 16; o; o >>= 1) {
        s  += __shfl_xor_sync(0xffffffffu, s,  o);
        s2 += __shfl_xor_sync(0xffffffffu, s2, o);
    }
    float mu  = s * (1.f / (float)CDV);
    float var = fmaxf(s2 * (1.f / (float)CDV) - mu * mu, 0.f) + EPSF;
    float rinv = rsqrtf(var);
    rinv = rinv * (1.5f - 0.5f * var * rinv * rinv);

    float acc[6] = {0.f, 0.f, 0.f, 0.f, 0.f, 0.f};
#pragma unroll
    for (int q = 0; q < 32; q++) {
        int k = lane + 32 * q;
        float zn = fmaf(s_g[k], (x[q] - mu) * rinv, s_b[k]);
#pragma unroll
        for (int o = 0; o < 6; o++)
            acc[o] = fmaf(zn, s_w[o * CDV + k], acc[o]);
    }
#pragma unroll
    for (int o = 0; o < 6; o++)
#pragma unroll
        for (int d = 16; d; d >>= 1)
            acc[o] += __shfl_xor_sync(0xffffffffu, acc[o], d);

    if (lane == 0) {
        float cvals[6], cs = 0.f;
#pragma unroll
        for (int o = 0; o < 6; o++) { cvals[o] = credit[r * 6 + o]; cs += cvals[o]; }
        float inv = (cs > 0.f) ? (1.f / cs) : 0.f;
#pragma unroll
        for (int o = 0; o < 6; o++) {
            float bias = (cs > 0.f) ? cvals[o] * inv : (1.f / 6.f);
            out[r * 6 + o] = acc[o] + s_ob[o] + bias;
        }
    }
}

// ---------------------------------------------------------------------------
extern "C" void kernel_launch(void* const* d_in, const int* in_sizes, int n_in,
                              void* d_out, int out_size) {
    const float* encode     = (const float*)d_in[0];
    const float* credit_vec = (const float*)d_in[1];
    const float* meta_table = (const float*)d_in[2];
    const float* conv_w     = (const float*)d_in[3];
    const float* conv_b     = (const float*)d_in[4];
    const float* ln1_g      = (const float*)d_in[5];
    const float* ln1_b      = (const float*)d_in[6];
    const float* mlp1_w     = (const float*)d_in[7];
    const float* mlp1_b     = (const float*)d_in[8];
    const float* ln2_g      = (const float*)d_in[9];
    const float* ln2_b      = (const float*)d_in[10];
    const float* out_w      = (const float*)d_in[11];
    const float* out_b      = (const float*)d_in[12];
    const int*   meta_ids   = (const int*)d_in[13];
    const int*   cat_ids    = (const int*)d_in[14];
    const int*   cat_seg    = (const int*)d_in[15];
    float*       out        = (float*)d_out;
    const int    ncat       = in_sizes[14];

    cudaFuncSetAttribute(gemm1_hmma,
                         cudaFuncAttributeMaxDynamicSharedMemorySize, SMEM_GEMM);

    meta_kernel<<<NB / 256, 256>>>(meta_table, conv_w, conv_b,
                                   meta_ids, cat_ids, cat_seg, ncat);
    wsplit_kernel<<<CDV / 8, 256>>>(mlp1_w);
    prep_kernel<<<NB / 8, 256>>>(encode, ln1_g, ln1_b);
    gemm1_hmma<<<(NB / BM) * (CDV / BN), 256, SMEM_GEMM>>>(mlp1_b);
    head_kernel<<<NB / 8, 256>>>(credit_vec, ln2_g, ln2_b, out_w, out_b, out);
}

// round 9
// speedup vs baseline: 6.9406x; 1.4018x over previous
// v7: single-pass fp16 HMMA GEMM1 + fp16 features (resubmission of v6; R6/R7 runs
// died in the GB300 broker before execution — no kernel signal).
#include <cuda_runtime.h>
#include <cuda_fp16.h>
#include <cstdint>

#define NB      32768      // batch
#define HH      512        // hidden
#define MDV     8          // meta embed dim
#define CDV     1024       // classifier dim
#define KIN     532        // H + 20
#define KPAD    576        // padded K
#define EPSF    1e-6f

// GEMM tiling
#define BM      128
#define BN      128
#define BK      32
#define NSTAGE  4
#define KCHUNKS 18         // 576 / 32

#define TSTRIDE 40                       // fp16 elems per smem row (80 B, conflict-free)
#define TILE_BYTES  (128 * TSTRIDE * 2)  // 10240
#define STAGE_BYTES (2 * TILE_BYTES)     // 20480 (A, W)
#define SMEM_GEMM   (NSTAGE * STAGE_BYTES) // 81920

// ---- scratch (static device globals; no runtime allocation) ----
__device__ float  g_meta_feat[NB * 20];
__device__ __half g_features[(size_t)NB * CDV];
__device__ __half g_Ah[(size_t)NB * KPAD];
__device__ __half g_Wh[(size_t)CDV * KPAD];

// ---------------------------------------------------------------------------
// PTX helpers (baseline PTX only — tcgen05 unavailable on this build)
// ---------------------------------------------------------------------------
__device__ __forceinline__ uint32_t smem_u32(const void* p) {
    uint32_t a;
    asm("{ .reg .u64 t; cvta.to.shared.u64 t, %1; cvt.u32.u64 %0, t; }"
        : "=r"(a) : "l"(p));
    return a;
}

__device__ __forceinline__ void cp16(uint32_t s, const void* g) {
    asm volatile("cp.async.cg.shared.global [%0], [%1], 16;" :: "r"(s), "l"(g));
}
__device__ __forceinline__ void cp_commit() {
    asm volatile("cp.async.commit_group;" ::: "memory");
}
template <int N>
__device__ __forceinline__ void cp_wait() {
    asm volatile("cp.async.wait_group %0;" :: "n"(N) : "memory");
}

__device__ __forceinline__ void ldsm4(uint32_t* r, uint32_t a) {
    asm volatile("ldmatrix.sync.aligned.m8n8.x4.shared.b16 {%0,%1,%2,%3}, [%4];"
                 : "=r"(r[0]), "=r"(r[1]), "=r"(r[2]), "=r"(r[3]) : "r"(a));
}

__device__ __forceinline__ void mma16816(float* c, const uint32_t* a, const uint32_t* b) {
    asm volatile("mma.sync.aligned.m16n8k16.row.col.f32.f16.f16.f32 "
                 "{%0,%1,%2,%3}, {%4,%5,%6,%7}, {%8,%9}, {%0,%1,%2,%3};"
                 : "+f"(c[0]), "+f"(c[1]), "+f"(c[2]), "+f"(c[3])
                 : "r"(a[0]), "r"(a[1]), "r"(a[2]), "r"(a[3]),
                   "r"(b[0]), "r"(b[1]));
}

// ---------------------------------------------------------------------------
// K1: meta path. One thread per example (22 us measured — fine).
// ---------------------------------------------------------------------------
__global__ void meta_kernel(const float* __restrict__ meta_table,
                            const float* __restrict__ conv_w,
                            const float* __restrict__ conv_b,
                            const int*   __restrict__ meta_ids,
                            const int*   __restrict__ cat_ids,
                            const int*   __restrict__ cat_seg,
                            int ncat) {
    __shared__ float s_cw[90];
    __shared__ float s_cb[5];
    if (threadIdx.x < 90) s_cw[threadIdx.x] = conv_w[threadIdx.x];
    if (threadIdx.x < 5)  s_cb[threadIdx.x] = conv_b[threadIdx.x];
    __syncthreads();

    int b = blockIdx.x * blockDim.x + threadIdx.x;
    if (b >= NB) return;

    int lo = 0, hi = ncat;
    while (lo < hi) { int m = (lo + hi) >> 1; if (cat_seg[m] < b) lo = m + 1; else hi = m; }
    int start = lo;
    hi = ncat;
    while (lo < hi) { int m = (lo + hi) >> 1; if (cat_seg[m] <= b) lo = m + 1; else hi = m; }
    int end = lo;

    float mm[6][8];
    float sum[8];
#pragma unroll
    for (int d = 0; d < 8; d++) sum[d] = 0.f;
    for (int j = start; j < end; j++) {
        int id = cat_ids[j];
        const float* row = meta_table + (size_t)id * MDV;
#pragma unroll
        for (int d = 0; d < 8; d++) sum[d] += __ldg(row + d);
    }
    float cnt = fmaxf((float)(end - start), 1.f);
    float rc = 1.f / cnt;
#pragma unroll
    for (int d = 0; d < 8; d++) mm[0][d] = sum[d] * rc;

#pragma unroll
    for (int r = 0; r < 5; r++) {
        int id = meta_ids[b * 5 + r];
        const float* row = meta_table + (size_t)id * MDV;
#pragma unroll
        for (int d = 0; d < 8; d++) mm[r + 1][d] = __ldg(row + d);
    }

    float mf[20];
#pragma unroll
    for (int o = 0; o < 5; o++) {
        float cv[6];
#pragma unroll
        for (int t = 0; t < 6; t++) {
            float acc = s_cb[o];
#pragma unroll
            for (int i = 0; i < 6; i++)
#pragma unroll
                for (int k = 0; k < 3; k++)
                    acc = fmaf(s_cw[(o * 6 + i) * 3 + k], mm[i][t + k], acc);
            cv[t] = fmaxf(acc, 0.f);
        }
#pragma unroll
        for (int t = 0; t < 4; t++)
            mf[o * 4 + t] = fmaxf(fmaxf(cv[t], cv[t + 1]), cv[t + 2]);
    }
#pragma unroll
    for (int q = 0; q < 20; q++) g_meta_feat[b * 20 + q] = mf[q];
}

// ---------------------------------------------------------------------------
// K2: LN1(concat(encode, meta_feat)) -> fp16 rows [NB][KPAD] (zero-padded).
// One warp per row.
// ---------------------------------------------------------------------------
__global__ void __launch_bounds__(256)
prep_kernel(const float* __restrict__ encode,
            const float* __restrict__ ln1_g,
            const float* __restrict__ ln1_b) {
    const int lane = threadIdx.x & 31;
    const int wid  = threadIdx.x >> 5;
    const int r    = blockIdx.x * 8 + wid;

    float x[18];
    float s = 0.f, s2 = 0.f;
#pragma unroll
    for (int q = 0; q < 18; q++) {
        int k = lane + 32 * q;
        float v = 0.f;
        if (k < KIN)
            v = (k < HH) ? encode[(size_t)r * HH + k]
                         : g_meta_feat[r * 20 + (k - HH)];
        x[q] = v;
        s += v; s2 = fmaf(v, v, s2);
    }
#pragma unroll
    for (int o = 16; o; o >>= 1) {
        s  += __shfl_xor_sync(0xffffffffu, s,  o);
        s2 += __shfl_xor_sync(0xffffffffu, s2, o);
    }
    float mu  = s * (1.f / (float)KIN);
    float var = fmaxf(s2 * (1.f / (float)KIN) - mu * mu, 0.f) + EPSF;
    float rinv = rsqrtf(var);
    rinv = rinv * (1.5f - 0.5f * var * rinv * rinv);

    __half* ah = g_Ah + (size_t)r * KPAD;
#pragma unroll
    for (int q = 0; q < 18; q++) {
        int k = lane + 32 * q;
        float v = 0.f;
        if (k < KIN)
            v = fmaf(__ldg(ln1_g + k), (x[q] - mu) * rinv, __ldg(ln1_b + k));
        ah[k] = __float2half_rn(v);
    }
}

// ---------------------------------------------------------------------------
// K3: W -> fp16 [CDV][KPAD], zero-padded.
// ---------------------------------------------------------------------------
__global__ void __launch_bounds__(256)
wconv_kernel(const float* __restrict__ mlp1_w) {
    const int lane = threadIdx.x & 31;
    const int wid  = threadIdx.x >> 5;
    const int r    = blockIdx.x * 8 + wid;

    __half* wh = g_Wh + (size_t)r * KPAD;
    for (int k = lane; k < KPAD; k += 32) {
        float v = (k < KIN) ? mlp1_w[(size_t)r * KIN + k] : 0.f;
        wh[k] = __float2half_rn(v);
    }
}

// ---------------------------------------------------------------------------
// K4: HMMA GEMM1: features = relu(A @ W^T + b), single-pass fp16.
// CTA 128x128, BK=32, 4-stage cp.async pipeline, 2 CTAs/SM. fp16 output.
// ---------------------------------------------------------------------------
__global__ void __launch_bounds__(256, 2)
gemm1_hmma(const float* __restrict__ mlp1_b) {
    extern __shared__ char smem[];
    const uint32_t sbase = smem_u32(smem);
    const int tid  = threadIdx.x;
    const int lane = tid & 31;
    const int wid  = tid >> 5;
    const int wm   = wid >> 1;          // 0..3 : 32-row slice
    const int wn   = wid & 1;           // 0..1 : 64-col slice
    const int mt   = blockIdx.x >> 3;
    const int nt   = blockIdx.x & 7;
    const int row0 = mt * BM;
    const int n0   = nt * BN;

    const __half* gsrc[2] = {
        g_Ah + (size_t)row0 * KPAD,
        g_Wh + (size_t)n0   * KPAD };

    auto load_stage = [&](int c, int st) {
        const int k0 = c * BK;
        const uint32_t sst = sbase + st * STAGE_BYTES;
#pragma unroll
        for (int t = 0; t < 2; t++) {
#pragma unroll
            for (int h = 0; h < 2; h++) {
                int idx = tid + h * 256;
                int row = idx >> 2, seg = idx & 3;
                cp16(sst + t * TILE_BYTES + (row * TSTRIDE + seg * 8) * 2,
                     gsrc[t] + (size_t)row * KPAD + k0 + seg * 8);
            }
        }
    };

    float acc[2][8][4];
#pragma unroll
    for (int i = 0; i < 2; i++)
#pragma unroll
        for (int j = 0; j < 8; j++)
#pragma unroll
            for (int e = 0; e < 4; e++) acc[i][j][e] = 0.f;

    load_stage(0, 0); cp_commit();
    load_stage(1, 1); cp_commit();
    load_stage(2, 2); cp_commit();

    // lane-dependent smem offsets (bytes)
    const uint32_t a_off0 = ((wm * 32 + (lane & 15)) * TSTRIDE + (lane >> 4) * 8) * 2;
    const uint32_t b_off0 = ((wn * 64 + ((lane >> 4) << 3) + (lane & 7)) * TSTRIDE
                             + (lane & 8)) * 2;

    for (int c = 0; c < KCHUNKS; c++) {
        cp_wait<NSTAGE - 2>();
        __syncthreads();
        if (c + 3 < KCHUNKS) load_stage(c + 3, (c + 3) % NSTAGE);
        cp_commit();

        const uint32_t aT = sbase + (c % NSTAGE) * STAGE_BYTES;
        const uint32_t bT = aT + TILE_BYTES;

#pragma unroll
        for (int ks = 0; ks < 2; ks++) {
            uint32_t af[2][4], bf[4][4];
#pragma unroll
            for (int mf = 0; mf < 2; mf++)
                ldsm4(af[mf], aT + a_off0 + (mf * 16 * TSTRIDE + ks * 16) * 2);
#pragma unroll
            for (int nf2 = 0; nf2 < 4; nf2++)
                ldsm4(bf[nf2], bT + b_off0 + (nf2 * 16 * TSTRIDE + ks * 16) * 2);
#pragma unroll
            for (int nf2 = 0; nf2 < 4; nf2++)
#pragma unroll
                for (int mf = 0; mf < 2; mf++) {
                    mma16816(acc[mf][2 * nf2 + 0], af[mf], bf[nf2] + 0);
                    mma16816(acc[mf][2 * nf2 + 1], af[mf], bf[nf2] + 2);
                }
        }
        __syncthreads();
    }

    // ---- epilogue: bias + relu, fp16 stores ----
    const int l4 = lane >> 2, l2 = lane & 3;
#pragma unroll
    for (int mf = 0; mf < 2; mf++) {
        int row = row0 + wm * 32 + mf * 16 + l4;
#pragma unroll
        for (int nf = 0; nf < 8; nf++) {
            int col = n0 + wn * 64 + nf * 8 + 2 * l2;
            float2 bb = *(const float2*)(mlp1_b + col);
            __half2 v0 = __floats2half2_rn(fmaxf(acc[mf][nf][0] + bb.x, 0.f),
                                           fmaxf(acc[mf][nf][1] + bb.y, 0.f));
            __half2 v1 = __floats2half2_rn(fmaxf(acc[mf][nf][2] + bb.x, 0.f),
                                           fmaxf(acc[mf][nf][3] + bb.y, 0.f));
            *(__half2*)(g_features + (size_t)row * CDV + col)       = v0;
            *(__half2*)(g_features + (size_t)(row + 8) * CDV + col) = v1;
        }
    }
}

// ---------------------------------------------------------------------------
// K5: LN2 + GEMM2 (1024 -> 6) + out_b + normalized credit biases.
// One warp per row; fp16 feature reads as half2.
// ---------------------------------------------------------------------------
__global__ void __launch_bounds__(256)
head_kernel(const float* __restrict__ credit,
            const float* __restrict__ ln2_g,
            const float* __restrict__ ln2_b,
            const float* __restrict__ out_w,
            const float* __restrict__ out_b,
            float* __restrict__ out) {
    __shared__ float s_w[6 * CDV];
    __shared__ float s_g[CDV];
    __shared__ float s_b[CDV];
    __shared__ float s_ob[6];
    for (int i = threadIdx.x; i < 6 * CDV; i += 256) s_w[i] = out_w[i];
    for (int i = threadIdx.x; i < CDV; i += 256) { s_g[i] = ln2_g[i]; s_b[i] = ln2_b[i]; }
    if (threadIdx.x < 6) s_ob[threadIdx.x] = out_b[threadIdx.x];
    __syncthreads();

    const int lane = threadIdx.x & 31;
    const int w    = threadIdx.x >> 5;
    const int r    = blockIdx.x * 8 + w;

    const __half2* f = (const __half2*)(g_features + (size_t)r * CDV);
    float2 x[16];
    float s = 0.f, s2 = 0.f;
#pragma unroll
    for (int q = 0; q < 16; q++) {
        x[q] = __half22float2(f[lane + 32 * q]);
        s += x[q].x + x[q].y;
        s2 = fmaf(x[q].x, x[q].x, fmaf(x[q].y, x[q].y, s2));
    }
#pragma unroll
    for (int o = 16; o; o >>= 1) {
        s  += __shfl_xor_sync(0xffffffffu, s,  o);
        s2 += __shfl_xor_sync(0xffffffffu, s2, o);
    }
    float mu  = s * (1.f / (float)CDV);
    float var = fmaxf(s2 * (1.f / (float)CDV) - mu * mu, 0.f) + EPSF;
    float rinv = rsqrtf(var);
    rinv = rinv * (1.5f - 0.5f * var * rinv * rinv);

    float acc[6] = {0.f, 0.f, 0.f, 0.f, 0.f, 0.f};
#pragma unroll
    for (int q = 0; q < 16; q++) {
        int k = 2 * (lane + 32 * q);
        float zn0 = fmaf(s_g[k],     (x[q].x - mu) * rinv, s_b[k]);
        float zn1 = fmaf(s_g[k + 1], (x[q].y - mu) * rinv, s_b[k + 1]);
#pragma unroll
        for (int o = 0; o < 6; o++) {
            acc[o] = fmaf(zn0, s_w[o * CDV + k],     acc[o]);
            acc[o] = fmaf(zn1, s_w[o * CDV + k + 1], acc[o]);
        }
    }
#pragma unroll
    for (int o = 0; o < 6; o++)
#pragma unroll
        for (int d = 16; d; d >>= 1)
            acc[o] += __shfl_xor_sync(0xffffffffu, acc[o], d);

    if (lane == 0) {
        float cvals[6], cs = 0.f;
#pragma unroll
        for (int o = 0; o < 6; o++) { cvals[o] = credit[r * 6 + o]; cs += cvals[o]; }
        float inv = (cs > 0.f) ? (1.f / cs) : 0.f;
#pragma unroll
        for (int o = 0; o < 6; o++) {
            float bias = (cs > 0.f) ? cvals[o] * inv : (1.f / 6.f);
            out[r * 6 + o] = acc[o] + s_ob[o] + bias;
        }
    }
}

// ---------------------------------------------------------------------------
extern "C" void kernel_launch(void* const* d_in, const int* in_sizes, int n_in,
                              void* d_out, int out_size) {
    const float* encode     = (const float*)d_in[0];
    const float* credit_vec = (const float*)d_in[1];
    const float* meta_table = (const float*)d_in[2];
    const float* conv_w     = (const float*)d_in[3];
    const float* conv_b     = (const float*)d_in[4];
    const float* ln1_g      = (const float*)d_in[5];
    const float* ln1_b      = (const float*)d_in[6];
    const float* mlp1_w     = (const float*)d_in[7];
    const float* mlp1_b     = (const float*)d_in[8];
    const float* ln2_g      = (const float*)d_in[9];
    const float* ln2_b      = (const float*)d_in[10];
    const float* out_w      = (const float*)d_in[11];
    const float* out_b      = (const float*)d_in[12];
    const int*   meta_ids   = (const int*)d_in[13];
    const int*   cat_ids    = (const int*)d_in[14];
    const int*   cat_seg    = (const int*)d_in[15];
    float*       out        = (float*)d_out;
    const int    ncat       = in_sizes[14];

    cudaFuncSetAttribute(gemm1_hmma,
                         cudaFuncAttributeMaxDynamicSharedMemorySize, SMEM_GEMM);

    meta_kernel<<<NB / 256, 256>>>(meta_table, conv_w, conv_b,
                                   meta_ids, cat_ids, cat_seg, ncat);
    wconv_kernel<<<CDV / 8, 256>>>(mlp1_w);
    prep_kernel<<<NB / 8, 256>>>(encode, ln1_g, ln1_b);
    gemm1_hmma<<<(NB / BM) * (CDV / BN), 256, SMEM_GEMM>>>(mlp1_b);
    head_kernel<<<NB / 8, 256>>>(credit_vec, ln2_g, ln2_b, out_w, out_b, out);
}

// round 11
// speedup vs baseline: 7.7949x; 1.1231x over previous
// v8: BK=64 / 2-stage pipeline (halve barrier count), head-kernel row reuse.
#include <cuda_runtime.h>
#include <cuda_fp16.h>
#include <cstdint>

#define NB      32768      // batch
#define HH      512        // hidden
#define MDV     8          // meta embed dim
#define CDV     1024       // classifier dim
#define KIN     532        // H + 20
#define KPAD    576        // padded K
#define EPSF    1e-6f

// GEMM tiling
#define BM      128
#define BN      128
#define BK      64
#define NSTAGE  2
#define KCHUNKS 9          // 576 / 64

#define TSTRIDE 72                       // fp16 elems per smem row (144 B, conflict-free)
#define TILE_BYTES  (128 * TSTRIDE * 2)  // 18432
#define STAGE_BYTES (2 * TILE_BYTES)     // 36864 (A, W)
#define SMEM_GEMM   (NSTAGE * STAGE_BYTES) // 73728

// ---- scratch (static device globals; no runtime allocation) ----
__device__ float  g_meta_feat[NB * 20];
__device__ __half g_features[(size_t)NB * CDV];
__device__ __half g_Ah[(size_t)NB * KPAD];
__device__ __half g_Wh[(size_t)CDV * KPAD];

// ---------------------------------------------------------------------------
// PTX helpers (baseline PTX only — tcgen05 unavailable on this build)
// ---------------------------------------------------------------------------
__device__ __forceinline__ uint32_t smem_u32(const void* p) {
    uint32_t a;
    asm("{ .reg .u64 t; cvta.to.shared.u64 t, %1; cvt.u32.u64 %0, t; }"
        : "=r"(a) : "l"(p));
    return a;
}

__device__ __forceinline__ void cp16(uint32_t s, const void* g) {
    asm volatile("cp.async.cg.shared.global [%0], [%1], 16;" :: "r"(s), "l"(g));
}
__device__ __forceinline__ void cp_commit() {
    asm volatile("cp.async.commit_group;" ::: "memory");
}
template <int N>
__device__ __forceinline__ void cp_wait() {
    asm volatile("cp.async.wait_group %0;" :: "n"(N) : "memory");
}

__device__ __forceinline__ void ldsm4(uint32_t* r, uint32_t a) {
    asm volatile("ldmatrix.sync.aligned.m8n8.x4.shared.b16 {%0,%1,%2,%3}, [%4];"
                 : "=r"(r[0]), "=r"(r[1]), "=r"(r[2]), "=r"(r[3]) : "r"(a));
}

__device__ __forceinline__ void mma16816(float* c, const uint32_t* a, const uint32_t* b) {
    asm volatile("mma.sync.aligned.m16n8k16.row.col.f32.f16.f16.f32 "
                 "{%0,%1,%2,%3}, {%4,%5,%6,%7}, {%8,%9}, {%0,%1,%2,%3};"
                 : "+f"(c[0]), "+f"(c[1]), "+f"(c[2]), "+f"(c[3])
                 : "r"(a[0]), "r"(a[1]), "r"(a[2]), "r"(a[3]),
                   "r"(b[0]), "r"(b[1]));
}

// ---------------------------------------------------------------------------
// K1: meta path. One thread per example.
// ---------------------------------------------------------------------------
__global__ void meta_kernel(const float* __restrict__ meta_table,
                            const float* __restrict__ conv_w,
                            const float* __restrict__ conv_b,
                            const int*   __restrict__ meta_ids,
                            const int*   __restrict__ cat_ids,
                            const int*   __restrict__ cat_seg,
                            int ncat) {
    __shared__ float s_cw[90];
    __shared__ float s_cb[5];
    if (threadIdx.x < 90) s_cw[threadIdx.x] = conv_w[threadIdx.x];
    if (threadIdx.x < 5)  s_cb[threadIdx.x] = conv_b[threadIdx.x];
    __syncthreads();

    int b = blockIdx.x * blockDim.x + threadIdx.x;
    if (b >= NB) return;

    int lo = 0, hi = ncat;
    while (lo < hi) { int m = (lo + hi) >> 1; if (cat_seg[m] < b) lo = m + 1; else hi = m; }
    int start = lo;
    hi = ncat;
    while (lo < hi) { int m = (lo + hi) >> 1; if (cat_seg[m] <= b) lo = m + 1; else hi = m; }
    int end = lo;

    float mm[6][8];
    float sum[8];
#pragma unroll
    for (int d = 0; d < 8; d++) sum[d] = 0.f;
    for (int j = start; j < end; j++) {
        int id = cat_ids[j];
        const float* row = meta_table + (size_t)id * MDV;
#pragma unroll
        for (int d = 0; d < 8; d++) sum[d] += __ldg(row + d);
    }
    float cnt = fmaxf((float)(end - start), 1.f);
    float rc = 1.f / cnt;
#pragma unroll
    for (int d = 0; d < 8; d++) mm[0][d] = sum[d] * rc;

#pragma unroll
    for (int r = 0; r < 5; r++) {
        int id = meta_ids[b * 5 + r];
        const float* row = meta_table + (size_t)id * MDV;
#pragma unroll
        for (int d = 0; d < 8; d++) mm[r + 1][d] = __ldg(row + d);
    }

    float mf[20];
#pragma unroll
    for (int o = 0; o < 5; o++) {
        float cv[6];
#pragma unroll
        for (int t = 0; t < 6; t++) {
            float acc = s_cb[o];
#pragma unroll
            for (int i = 0; i < 6; i++)
#pragma unroll
                for (int k = 0; k < 3; k++)
                    acc = fmaf(s_cw[(o * 6 + i) * 3 + k], mm[i][t + k], acc);
            cv[t] = fmaxf(acc, 0.f);
        }
#pragma unroll
        for (int t = 0; t < 4; t++)
            mf[o * 4 + t] = fmaxf(fmaxf(cv[t], cv[t + 1]), cv[t + 2]);
    }
#pragma unroll
    for (int q = 0; q < 20; q++) g_meta_feat[b * 20 + q] = mf[q];
}

// ---------------------------------------------------------------------------
// K2: LN1(concat(encode, meta_feat)) -> fp16 rows [NB][KPAD] (zero-padded).
// ---------------------------------------------------------------------------
__global__ void __launch_bounds__(256)
prep_kernel(const float* __restrict__ encode,
            const float* __restrict__ ln1_g,
            const float* __restrict__ ln1_b) {
    const int lane = threadIdx.x & 31;
    const int wid  = threadIdx.x >> 5;
    const int r    = blockIdx.x * 8 + wid;

    float x[18];
    float s = 0.f, s2 = 0.f;
#pragma unroll
    for (int q = 0; q < 18; q++) {
        int k = lane + 32 * q;
        float v = 0.f;
        if (k < KIN)
            v = (k < HH) ? encode[(size_t)r * HH + k]
                         : g_meta_feat[r * 20 + (k - HH)];
        x[q] = v;
        s += v; s2 = fmaf(v, v, s2);
    }
#pragma unroll
    for (int o = 16; o; o >>= 1) {
        s  += __shfl_xor_sync(0xffffffffu, s,  o);
        s2 += __shfl_xor_sync(0xffffffffu, s2, o);
    }
    float mu  = s * (1.f / (float)KIN);
    float var = fmaxf(s2 * (1.f / (float)KIN) - mu * mu, 0.f) + EPSF;
    float rinv = rsqrtf(var);
    rinv = rinv * (1.5f - 0.5f * var * rinv * rinv);

    __half* ah = g_Ah + (size_t)r * KPAD;
#pragma unroll
    for (int q = 0; q < 18; q++) {
        int k = lane + 32 * q;
        float v = 0.f;
        if (k < KIN)
            v = fmaf(__ldg(ln1_g + k), (x[q] - mu) * rinv, __ldg(ln1_b + k));
        ah[k] = __float2half_rn(v);
    }
}

// ---------------------------------------------------------------------------
// K3: W -> fp16 [CDV][KPAD], zero-padded.
// ---------------------------------------------------------------------------
__global__ void __launch_bounds__(256)
wconv_kernel(const float* __restrict__ mlp1_w) {
    const int lane = threadIdx.x & 31;
    const int wid  = threadIdx.x >> 5;
    const int r    = blockIdx.x * 8 + wid;

    __half* wh = g_Wh + (size_t)r * KPAD;
    for (int k = lane; k < KPAD; k += 32) {
        float v = (k < KIN) ? mlp1_w[(size_t)r * KIN + k] : 0.f;
        wh[k] = __float2half_rn(v);
    }
}

// ---------------------------------------------------------------------------
// K4: HMMA GEMM1: features = relu(A @ W^T + b), single-pass fp16.
// CTA 128x128, BK=64, 2-stage cp.async double buffer, 2 CTAs/SM. fp16 out.
// ---------------------------------------------------------------------------
__global__ void __launch_bounds__(256, 2)
gemm1_hmma(const float* __restrict__ mlp1_b) {
    extern __shared__ char smem[];
    const uint32_t sbase = smem_u32(smem);
    const int tid  = threadIdx.x;
    const int lane = tid & 31;
    const int wid  = tid >> 5;
    const int wm   = wid >> 1;          // 0..3 : 32-row slice
    const int wn   = wid & 1;           // 0..1 : 64-col slice
    const int mt   = blockIdx.x >> 3;
    const int nt   = blockIdx.x & 7;
    const int row0 = mt * BM;
    const int n0   = nt * BN;

    const __half* gsrc[2] = {
        g_Ah + (size_t)row0 * KPAD,
        g_Wh + (size_t)n0   * KPAD };

    // stage loader: 2 tiles x 128 rows x 8 segs(16B) = 2048 cp16, 8/thread
    auto load_stage = [&](int c, int st) {
        const int k0 = c * BK;
        const uint32_t sst = sbase + st * STAGE_BYTES;
#pragma unroll
        for (int t = 0; t < 2; t++) {
#pragma unroll
            for (int h = 0; h < 4; h++) {
                int idx = tid + h * 256;          // 0..1023
                int row = idx >> 3, seg = idx & 7;
                cp16(sst + t * TILE_BYTES + (row * TSTRIDE + seg * 8) * 2,
                     gsrc[t] + (size_t)row * KPAD + k0 + seg * 8);
            }
        }
    };

    float acc[2][8][4];
#pragma unroll
    for (int i = 0; i < 2; i++)
#pragma unroll
        for (int j = 0; j < 8; j++)
#pragma unroll
            for (int e = 0; e < 4; e++) acc[i][j][e] = 0.f;

    load_stage(0, 0); cp_commit();

    // lane-dependent smem offsets (bytes)
    const uint32_t a_off0 = ((wm * 32 + (lane & 15)) * TSTRIDE + (lane >> 4) * 8) * 2;
    const uint32_t b_off0 = ((wn * 64 + ((lane >> 4) << 3) + (lane & 7)) * TSTRIDE
                             + (lane & 8)) * 2;

    for (int c = 0; c < KCHUNKS; c++) {
        if (c + 1 < KCHUNKS) { load_stage(c + 1, (c + 1) & 1); cp_commit(); }
        cp_wait<1>();                    // stage c resident (c+1 in flight)
        __syncthreads();

        const uint32_t aT = sbase + (c & 1) * STAGE_BYTES;
        const uint32_t bT = aT + TILE_BYTES;

#pragma unroll
        for (int ks = 0; ks < 4; ks++) {
            uint32_t af[2][4], bf[4][4];
#pragma unroll
            for (int mf = 0; mf < 2; mf++)
                ldsm4(af[mf], aT + a_off0 + (mf * 16 * TSTRIDE + ks * 16) * 2);
#pragma unroll
            for (int nf2 = 0; nf2 < 4; nf2++)
                ldsm4(bf[nf2], bT + b_off0 + (nf2 * 16 * TSTRIDE + ks * 16) * 2);
#pragma unroll
            for (int nf2 = 0; nf2 < 4; nf2++)
#pragma unroll
                for (int mf = 0; mf < 2; mf++) {
                    mma16816(acc[mf][2 * nf2 + 0], af[mf], bf[nf2] + 0);
                    mma16816(acc[mf][2 * nf2 + 1], af[mf], bf[nf2] + 2);
                }
        }
        __syncthreads();                 // all warps done before buffer reuse
    }

    // ---- epilogue: bias + relu, fp16 stores ----
    const int l4 = lane >> 2, l2 = lane & 3;
#pragma unroll
    for (int mf = 0; mf < 2; mf++) {
        int row = row0 + wm * 32 + mf * 16 + l4;
#pragma unroll
        for (int nf = 0; nf < 8; nf++) {
            int col = n0 + wn * 64 + nf * 8 + 2 * l2;
            float2 bb = *(const float2*)(mlp1_b + col);
            __half2 v0 = __floats2half2_rn(fmaxf(acc[mf][nf][0] + bb.x, 0.f),
                                           fmaxf(acc[mf][nf][1] + bb.y, 0.f));
            __half2 v1 = __floats2half2_rn(fmaxf(acc[mf][nf][2] + bb.x, 0.f),
                                           fmaxf(acc[mf][nf][3] + bb.y, 0.f));
            *(__half2*)(g_features + (size_t)row * CDV + col)       = v0;
            *(__half2*)(g_features + (size_t)(row + 8) * CDV + col) = v1;
        }
    }
}

// ---------------------------------------------------------------------------
// K5: LN2 + GEMM2 (1024 -> 6) + out_b + normalized credit biases.
// 32 rows per block (warp x 4 sequential) to amortize the smem weight preload.
// ---------------------------------------------------------------------------
__global__ void __launch_bounds__(256)
head_kernel(const float* __restrict__ credit,
            const float* __restrict__ ln2_g,
            const float* __restrict__ ln2_b,
            const float* __restrict__ out_w,
            const float* __restrict__ out_b,
            float* __restrict__ out) {
    __shared__ float s_w[6 * CDV];
    __shared__ float s_g[CDV];
    __shared__ float s_b[CDV];
    __shared__ float s_ob[6];
    for (int i = threadIdx.x; i < 6 * CDV; i += 256) s_w[i] = out_w[i];
    for (int i = threadIdx.x; i < CDV; i += 256) { s_g[i] = ln2_g[i]; s_b[i] = ln2_b[i]; }
    if (threadIdx.x < 6) s_ob[threadIdx.x] = out_b[threadIdx.x];
    __syncthreads();

    const int lane = threadIdx.x & 31;
    const int w    = threadIdx.x >> 5;

    for (int rr = 0; rr < 4; rr++) {
        const int r = blockIdx.x * 32 + w * 4 + rr;

        const __half2* f = (const __half2*)(g_features + (size_t)r * CDV);
        float2 x[16];
        float s = 0.f, s2 = 0.f;
#pragma unroll
        for (int q = 0; q < 16; q++) {
            x[q] = __half22float2(f[lane + 32 * q]);
            s += x[q].x + x[q].y;
            s2 = fmaf(x[q].x, x[q].x, fmaf(x[q].y, x[q].y, s2));
        }
#pragma unroll
        for (int o = 16; o; o >>= 1) {
            s  += __shfl_xor_sync(0xffffffffu, s,  o);
            s2 += __shfl_xor_sync(0xffffffffu, s2, o);
        }
        float mu  = s * (1.f / (float)CDV);
        float var = fmaxf(s2 * (1.f / (float)CDV) - mu * mu, 0.f) + EPSF;
        float rinv = rsqrtf(var);
        rinv = rinv * (1.5f - 0.5f * var * rinv * rinv);

        float acc[6] = {0.f, 0.f, 0.f, 0.f, 0.f, 0.f};
#pragma unroll
        for (int q = 0; q < 16; q++) {
            int k = 2 * (lane + 32 * q);
            float zn0 = fmaf(s_g[k],     (x[q].x - mu) * rinv, s_b[k]);
            float zn1 = fmaf(s_g[k + 1], (x[q].y - mu) * rinv, s_b[k + 1]);
#pragma unroll
            for (int o = 0; o < 6; o++) {
                acc[o] = fmaf(zn0, s_w[o * CDV + k],     acc[o]);
                acc[o] = fmaf(zn1, s_w[o * CDV + k + 1], acc[o]);
            }
        }
#pragma unroll
        for (int o = 0; o < 6; o++)
#pragma unroll
            for (int d = 16; d; d >>= 1)
                acc[o] += __shfl_xor_sync(0xffffffffu, acc[o], d);

        if (lane == 0) {
            float cvals[6], cs = 0.f;
#pragma unroll
            for (int o = 0; o < 6; o++) { cvals[o] = credit[r * 6 + o]; cs += cvals[o]; }
            float inv = (cs > 0.f) ? (1.f / cs) : 0.f;
#pragma unroll
            for (int o = 0; o < 6; o++) {
                float bias = (cs > 0.f) ? cvals[o] * inv : (1.f / 6.f);
                out[r * 6 + o] = acc[o] + s_ob[o] + bias;
            }
        }
    }
}

// ---------------------------------------------------------------------------
extern "C" void kernel_launch(void* const* d_in, const int* in_sizes, int n_in,
                              void* d_out, int out_size) {
    const float* encode     = (const float*)d_in[0];
    const float* credit_vec = (const float*)d_in[1];
    const float* meta_table = (const float*)d_in[2];
    const float* conv_w     = (const float*)d_in[3];
    const float* conv_b     = (const float*)d_in[4];
    const float* ln1_g      = (const float*)d_in[5];
    const float* ln1_b      = (const float*)d_in[6];
    const float* mlp1_w     = (const float*)d_in[7];
    const float* mlp1_b     = (const float*)d_in[8];
    const float* ln2_g      = (const float*)d_in[9];
    const float* ln2_b      = (const float*)d_in[10];
    const float* out_w      = (const float*)d_in[11];
    const float* out_b      = (const float*)d_in[12];
    const int*   meta_ids   = (const int*)d_in[13];
    const int*   cat_ids    = (const int*)d_in[14];
    const int*   cat_seg    = (const int*)d_in[15];
    float*       out        = (float*)d_out;
    const int    ncat       = in_sizes[14];

    cudaFuncSetAttribute(gemm1_hmma,
                         cudaFuncAttributeMaxDynamicSharedMemorySize, SMEM_GEMM);

    meta_kernel<<<NB / 256, 256>>>(meta_table, conv_w, conv_b,
                                   meta_ids, cat_ids, cat_seg, ncat);
    wconv_kernel<<<CDV / 8, 256>>>(mlp1_w);
    prep_kernel<<<NB / 8, 256>>>(encode, ln1_g, ln1_b);
    gemm1_hmma<<<(NB / BM) * (CDV / BN), 256, SMEM_GEMM>>>(mlp1_b);
    head_kernel<<<NB / 32, 256>>>(credit_vec, ln2_g, ln2_b, out_w, out_b, out);
}

// round 13
// speedup vs baseline: 7.9419x; 1.0189x over previous
// v10: v9 with the cp.async acquire fix — wait THEN sync, issue after barrier.
#include <cuda_runtime.h>
#include <cuda_fp16.h>
#include <cstdint>

#define NB      32768      // batch
#define HH      512        // hidden
#define MDV     8          // meta embed dim
#define CDV     1024       // classifier dim
#define KIN     532        // H + 20
#define KPAD    576        // padded K
#define EPSF    1e-6f

// GEMM tiling
#define BM      128
#define BN      128
#define BK      64
#define NSTAGE  3
#define KCHUNKS 9          // 576 / 64

#define TSTRIDE 72                       // fp16 elems per smem row (144 B, conflict-free)
#define TILE_BYTES  (128 * TSTRIDE * 2)  // 18432
#define STAGE_BYTES (2 * TILE_BYTES)     // 36864 (A, W)
#define SMEM_GEMM   (NSTAGE * STAGE_BYTES) // 110592

// ---- scratch (static device globals; no runtime allocation) ----
__device__ float  g_meta_feat[NB * 20];
__device__ __half g_features[(size_t)NB * CDV];
__device__ __half g_Ah[(size_t)NB * KPAD];
__device__ __half g_Wh[(size_t)CDV * KPAD];
__device__ int    g_seg_start[NB];
__device__ int    g_seg_end[NB];

// ---------------------------------------------------------------------------
// PTX helpers
// ---------------------------------------------------------------------------
__device__ __forceinline__ uint32_t smem_u32(const void* p) {
    uint32_t a;
    asm("{ .reg .u64 t; cvta.to.shared.u64 t, %1; cvt.u32.u64 %0, t; }"
        : "=r"(a) : "l"(p));
    return a;
}

__device__ __forceinline__ void cp16(uint32_t s, const void* g) {
    asm volatile("cp.async.cg.shared.global [%0], [%1], 16;" :: "r"(s), "l"(g));
}
__device__ __forceinline__ void cp_commit() {
    asm volatile("cp.async.commit_group;" ::: "memory");
}
template <int N>
__device__ __forceinline__ void cp_wait() {
    asm volatile("cp.async.wait_group %0;" :: "n"(N) : "memory");
}

__device__ __forceinline__ void ldsm4(uint32_t* r, uint32_t a) {
    asm volatile("ldmatrix.sync.aligned.m8n8.x4.shared.b16 {%0,%1,%2,%3}, [%4];"
                 : "=r"(r[0]), "=r"(r[1]), "=r"(r[2]), "=r"(r[3]) : "r"(a));
}

__device__ __forceinline__ void mma16816(float* c, const uint32_t* a, const uint32_t* b) {
    asm volatile("mma.sync.aligned.m16n8k16.row.col.f32.f16.f16.f32 "
                 "{%0,%1,%2,%3}, {%4,%5,%6,%7}, {%8,%9}, {%0,%1,%2,%3};"
                 : "+f"(c[0]), "+f"(c[1]), "+f"(c[2]), "+f"(c[3])
                 : "r"(a[0]), "r"(a[1]), "r"(a[2]), "r"(a[3]),
                   "r"(b[0]), "r"(b[1]));
}

// ---------------------------------------------------------------------------
// K0: segment boundary scatter over sorted cat_seg (replaces binary search).
// ---------------------------------------------------------------------------
__global__ void __launch_bounds__(256)
seg_bounds_kernel(const int* __restrict__ cat_seg, int ncat) {
    int i = blockIdx.x * 256 + threadIdx.x;
    if (i >= ncat) return;
    int s = cat_seg[i];
    if (i == 0 || cat_seg[i - 1] != s) g_seg_start[s] = i;
    if (i == ncat - 1 || cat_seg[i + 1] != s) g_seg_end[s] = i + 1;
}

// ---------------------------------------------------------------------------
// K1: meta path. One thread per example; segment bounds precomputed.
// ---------------------------------------------------------------------------
__global__ void meta_kernel(const float* __restrict__ meta_table,
                            const float* __restrict__ conv_w,
                            const float* __restrict__ conv_b,
                            const int*   __restrict__ meta_ids,
                            const int*   __restrict__ cat_ids) {
    __shared__ float s_cw[90];
    __shared__ float s_cb[5];
    if (threadIdx.x < 90) s_cw[threadIdx.x] = conv_w[threadIdx.x];
    if (threadIdx.x < 5)  s_cb[threadIdx.x] = conv_b[threadIdx.x];
    __syncthreads();

    int b = blockIdx.x * blockDim.x + threadIdx.x;
    if (b >= NB) return;

    int start = g_seg_start[b];
    int end   = g_seg_end[b];

    float mm[6][8];
    float sum[8];
#pragma unroll
    for (int d = 0; d < 8; d++) sum[d] = 0.f;
    for (int j = start; j < end; j++) {
        int id = cat_ids[j];
        const float* row = meta_table + (size_t)id * MDV;
#pragma unroll
        for (int d = 0; d < 8; d++) sum[d] += __ldg(row + d);
    }
    float cnt = fmaxf((float)(end - start), 1.f);
    float rc = 1.f / cnt;
#pragma unroll
    for (int d = 0; d < 8; d++) mm[0][d] = sum[d] * rc;

#pragma unroll
    for (int r = 0; r < 5; r++) {
        int id = meta_ids[b * 5 + r];
        const float* row = meta_table + (size_t)id * MDV;
#pragma unroll
        for (int d = 0; d < 8; d++) mm[r + 1][d] = __ldg(row + d);
    }

    float mf[20];
#pragma unroll
    for (int o = 0; o < 5; o++) {
        float cv[6];
#pragma unroll
        for (int t = 0; t < 6; t++) {
            float acc = s_cb[o];
#pragma unroll
            for (int i = 0; i < 6; i++)
#pragma unroll
                for (int k = 0; k < 3; k++)
                    acc = fmaf(s_cw[(o * 6 + i) * 3 + k], mm[i][t + k], acc);
            cv[t] = fmaxf(acc, 0.f);
        }
#pragma unroll
        for (int t = 0; t < 4; t++)
            mf[o * 4 + t] = fmaxf(fmaxf(cv[t], cv[t + 1]), cv[t + 2]);
    }
#pragma unroll
    for (int q = 0; q < 20; q++) g_meta_feat[b * 20 + q] = mf[q];
}

// ---------------------------------------------------------------------------
// K2: LN1(concat(encode, meta_feat)) -> fp16 rows [NB][KPAD] (zero-padded).
// ---------------------------------------------------------------------------
__global__ void __launch_bounds__(256)
prep_kernel(const float* __restrict__ encode,
            const float* __restrict__ ln1_g,
            const float* __restrict__ ln1_b) {
    const int lane = threadIdx.x & 31;
    const int wid  = threadIdx.x >> 5;
    const int r    = blockIdx.x * 8 + wid;

    float x[18];
    float s = 0.f, s2 = 0.f;
#pragma unroll
    for (int q = 0; q < 18; q++) {
        int k = lane + 32 * q;
        float v = 0.f;
        if (k < KIN)
            v = (k < HH) ? encode[(size_t)r * HH + k]
                         : g_meta_feat[r * 20 + (k - HH)];
        x[q] = v;
        s += v; s2 = fmaf(v, v, s2);
    }
#pragma unroll
    for (int o = 16; o; o >>= 1) {
        s  += __shfl_xor_sync(0xffffffffu, s,  o);
        s2 += __shfl_xor_sync(0xffffffffu, s2, o);
    }
    float mu  = s * (1.f / (float)KIN);
    float var = fmaxf(s2 * (1.f / (float)KIN) - mu * mu, 0.f) + EPSF;
    float rinv = rsqrtf(var);
    rinv = rinv * (1.5f - 0.5f * var * rinv * rinv);

    __half* ah = g_Ah + (size_t)r * KPAD;
#pragma unroll
    for (int q = 0; q < 18; q++) {
        int k = lane + 32 * q;
        float v = 0.f;
        if (k < KIN)
            v = fmaf(__ldg(ln1_g + k), (x[q] - mu) * rinv, __ldg(ln1_b + k));
        ah[k] = __float2half_rn(v);
    }
}

// ---------------------------------------------------------------------------
// K3: W -> fp16 [CDV][KPAD] + init of segment-bounds arrays (32768 thr = NB).
// ---------------------------------------------------------------------------
__global__ void __launch_bounds__(256)
wconv_kernel(const float* __restrict__ mlp1_w) {
    const int t = blockIdx.x * 256 + threadIdx.x;    // 0..32767
    g_seg_start[t] = 0;
    g_seg_end[t]   = 0;

    const int lane = threadIdx.x & 31;
    const int wid  = threadIdx.x >> 5;
    const int r    = blockIdx.x * 8 + wid;           // 0..1023 over 128 blocks
    if (r < CDV) {
        __half* wh = g_Wh + (size_t)r * KPAD;
        for (int k = lane; k < KPAD; k += 32) {
            float v = (k < KIN) ? mlp1_w[(size_t)r * KIN + k] : 0.f;
            wh[k] = __float2half_rn(v);
        }
    }
}

// ---------------------------------------------------------------------------
// K4: HMMA GEMM1: features = relu(A @ W^T + b), single-pass fp16.
// CTA 128x128, BK=64, 3-stage cp.async, one barrier per chunk (wait->sync),
// 2 CTAs/SM, fp16 output.
// ---------------------------------------------------------------------------
__global__ void __launch_bounds__(256, 2)
gemm1_hmma(const float* __restrict__ mlp1_b) {
    extern __shared__ char smem[];
    const uint32_t sbase = smem_u32(smem);
    const int tid  = threadIdx.x;
    const int lane = tid & 31;
    const int wid  = tid >> 5;
    const int wm   = wid >> 1;          // 0..3 : 32-row slice
    const int wn   = wid & 1;           // 0..1 : 64-col slice
    const int mt   = blockIdx.x >> 3;
    const int nt   = blockIdx.x & 7;
    const int row0 = mt * BM;
    const int n0   = nt * BN;

    const __half* gsrc[2] = {
        g_Ah + (size_t)row0 * KPAD,
        g_Wh + (size_t)n0   * KPAD };

    auto load_stage = [&](int c, int st) {
        const int k0 = c * BK;
        const uint32_t sst = sbase + st * STAGE_BYTES;
#pragma unroll
        for (int t = 0; t < 2; t++) {
#pragma unroll
            for (int h = 0; h < 4; h++) {
                int idx = tid + h * 256;          // 0..1023
                int row = idx >> 3, seg = idx & 7;
                cp16(sst + t * TILE_BYTES + (row * TSTRIDE + seg * 8) * 2,
                     gsrc[t] + (size_t)row * KPAD + k0 + seg * 8);
            }
        }
    };

    float acc[2][8][4];
#pragma unroll
    for (int i = 0; i < 2; i++)
#pragma unroll
        for (int j = 0; j < 8; j++)
#pragma unroll
            for (int e = 0; e < 4; e++) acc[i][j][e] = 0.f;

    load_stage(0, 0); cp_commit();
    load_stage(1, 1); cp_commit();

    // lane-dependent smem offsets (bytes)
    const uint32_t a_off0 = ((wm * 32 + (lane & 15)) * TSTRIDE + (lane >> 4) * 8) * 2;
    const uint32_t b_off0 = ((wn * 64 + ((lane >> 4) << 3) + (lane & 7)) * TSTRIDE
                             + (lane & 8)) * 2;

    for (int c = 0; c < KCHUNKS; c++) {
        // ACQUIRE: my stage-c group done, then barrier => ALL threads' stage-c
        // copies visible, and every warp has finished chunk c-1's MMAs.
        cp_wait<NSTAGE - 2>();
        __syncthreads();
        // Slot (c+2)%3 == slot (c-1)%3 is now safe to overwrite (post-barrier).
        if (c + 2 < KCHUNKS) load_stage(c + 2, (c + 2) % NSTAGE);
        cp_commit();

        const uint32_t aT = sbase + (c % NSTAGE) * STAGE_BYTES;
        const uint32_t bT = aT + TILE_BYTES;

#pragma unroll
        for (int ks = 0; ks < 4; ks++) {
            uint32_t af[2][4], bf[4][4];
#pragma unroll
            for (int mf = 0; mf < 2; mf++)
                ldsm4(af[mf], aT + a_off0 + (mf * 16 * TSTRIDE + ks * 16) * 2);
#pragma unroll
            for (int nf2 = 0; nf2 < 4; nf2++)
                ldsm4(bf[nf2], bT + b_off0 + (nf2 * 16 * TSTRIDE + ks * 16) * 2);
#pragma unroll
            for (int nf2 = 0; nf2 < 4; nf2++)
#pragma unroll
                for (int mf = 0; mf < 2; mf++) {
                    mma16816(acc[mf][2 * nf2 + 0], af[mf], bf[nf2] + 0);
                    mma16816(acc[mf][2 * nf2 + 1], af[mf], bf[nf2] + 2);
                }
        }
    }

    // ---- epilogue: bias + relu, fp16 stores ----
    const int l4 = lane >> 2, l2 = lane & 3;
#pragma unroll
    for (int mf = 0; mf < 2; mf++) {
        int row = row0 + wm * 32 + mf * 16 + l4;
#pragma unroll
        for (int nf = 0; nf < 8; nf++) {
            int col = n0 + wn * 64 + nf * 8 + 2 * l2;
            float2 bb = *(const float2*)(mlp1_b + col);
            __half2 v0 = __floats2half2_rn(fmaxf(acc[mf][nf][0] + bb.x, 0.f),
                                           fmaxf(acc[mf][nf][1] + bb.y, 0.f));
            __half2 v1 = __floats2half2_rn(fmaxf(acc[mf][nf][2] + bb.x, 0.f),
                                           fmaxf(acc[mf][nf][3] + bb.y, 0.f));
            *(__half2*)(g_features + (size_t)row * CDV + col)       = v0;
            *(__half2*)(g_features + (size_t)(row + 8) * CDV + col) = v1;
        }
    }
}

// ---------------------------------------------------------------------------
// K5: LN2 + GEMM2 (1024 -> 6) + out_b + normalized credit biases.
// 32 rows per block (warp x 4 sequential) to amortize smem weight preload.
// ---------------------------------------------------------------------------
__global__ void __launch_bounds__(256)
head_kernel(const float* __restrict__ credit,
            const float* __restrict__ ln2_g,
            const float* __restrict__ ln2_b,
            const float* __restrict__ out_w,
            const float* __restrict__ out_b,
            float* __restrict__ out) {
    __shared__ float s_w[6 * CDV];
    __shared__ float s_g[CDV];
    __shared__ float s_b[CDV];
    __shared__ float s_ob[6];
    for (int i = threadIdx.x; i < 6 * CDV; i += 256) s_w[i] = out_w[i];
    for (int i = threadIdx.x; i < CDV; i += 256) { s_g[i] = ln2_g[i]; s_b[i] = ln2_b[i]; }
    if (threadIdx.x < 6) s_ob[threadIdx.x] = out_b[threadIdx.x];
    __syncthreads();

    const int lane = threadIdx.x & 31;
    const int w    = threadIdx.x >> 5;

    for (int rr = 0; rr < 4; rr++) {
        const int r = blockIdx.x * 32 + w * 4 + rr;

        const __half2* f = (const __half2*)(g_features + (size_t)r * CDV);
        float2 x[16];
        float s = 0.f, s2 = 0.f;
#pragma unroll
        for (int q = 0; q < 16; q++) {
            x[q] = __half22float2(f[lane + 32 * q]);
            s += x[q].x + x[q].y;
            s2 = fmaf(x[q].x, x[q].x, fmaf(x[q].y, x[q].y, s2));
        }
#pragma unroll
        for (int o = 16; o; o >>= 1) {
            s  += __shfl_xor_sync(0xffffffffu, s,  o);
            s2 += __shfl_xor_sync(0xffffffffu, s2, o);
        }
        float mu  = s * (1.f / (float)CDV);
        float var = fmaxf(s2 * (1.f / (float)CDV) - mu * mu, 0.f) + EPSF;
        float rinv = rsqrtf(var);
        rinv = rinv * (1.5f - 0.5f * var * rinv * rinv);

        float acc[6] = {0.f, 0.f, 0.f, 0.f, 0.f, 0.f};
#pragma unroll
        for (int q = 0; q < 16; q++) {
            int k = 2 * (lane + 32 * q);
            float zn0 = fmaf(s_g[k],     (x[q].x - mu) * rinv, s_b[k]);
            float zn1 = fmaf(s_g[k + 1], (x[q].y - mu) * rinv, s_b[k + 1]);
#pragma unroll
            for (int o = 0; o < 6; o++) {
                acc[o] = fmaf(zn0, s_w[o * CDV + k],     acc[o]);
                acc[o] = fmaf(zn1, s_w[o * CDV + k + 1], acc[o]);
            }
        }
#pragma unroll
        for (int o = 0; o < 6; o++)
#pragma unroll
            for (int d = 16; d; d >>= 1)
                acc[o] += __shfl_xor_sync(0xffffffffu, acc[o], d);

        if (lane == 0) {
            float cvals[6], cs = 0.f;
#pragma unroll
            for (int o = 0; o < 6; o++) { cvals[o] = credit[r * 6 + o]; cs += cvals[o]; }
            float inv = (cs > 0.f) ? (1.f / cs) : 0.f;
#pragma unroll
            for (int o = 0; o < 6; o++) {
                float bias = (cs > 0.f) ? cvals[o] * inv : (1.f / 6.f);
                out[r * 6 + o] = acc[o] + s_ob[o] + bias;
            }
        }
    }
}

// ---------------------------------------------------------------------------
extern "C" void kernel_launch(void* const* d_in, const int* in_sizes, int n_in,
                              void* d_out, int out_size) {
    const float* encode     = (const float*)d_in[0];
    const float* credit_vec = (const float*)d_in[1];
    const float* meta_table = (const float*)d_in[2];
    const float* conv_w     = (const float*)d_in[3];
    const float* conv_b     = (const float*)d_in[4];
    const float* ln1_g      = (const float*)d_in[5];
    const float* ln1_b      = (const float*)d_in[6];
    const float* mlp1_w     = (const float*)d_in[7];
    const float* mlp1_b     = (const float*)d_in[8];
    const float* ln2_g      = (const float*)d_in[9];
    const float* ln2_b      = (const float*)d_in[10];
    const float* out_w      = (const float*)d_in[11];
    const float* out_b      = (const float*)d_in[12];
    const int*   meta_ids   = (const int*)d_in[13];
    const int*   cat_ids    = (const int*)d_in[14];
    const int*   cat_seg    = (const int*)d_in[15];
    float*       out        = (float*)d_out;
    const int    ncat       = in_sizes[14];

    cudaFuncSetAttribute(gemm1_hmma,
                         cudaFuncAttributeMaxDynamicSharedMemorySize, SMEM_GEMM);

    wconv_kernel<<<NB / 256, 256>>>(mlp1_w);        // also zeroes seg bounds
    seg_bounds_kernel<<<(ncat + 255) / 256, 256>>>(cat_seg, ncat);
    meta_kernel<<<NB / 256, 256>>>(meta_table, conv_w, conv_b,
                                   meta_ids, cat_ids);
    prep_kernel<<<NB / 8, 256>>>(encode, ln1_g, ln1_b);
    gemm1_hmma<<<(NB / BM) * (CDV / BN), 256, SMEM_GEMM>>>(mlp1_b);
    head_kernel<<<NB / 32, 256>>>(credit_vec, ln2_g, ln2_b, out_w, out_b, out);
}